// round 14
// baseline (speedup 1.0000x reference)
#include <cuda_runtime.h>
#include <cuda_bf16.h>
#include <math.h>

// ---------------- Problem dims ----------------
#define BB 512
#define TT 512
#define VV 50000
#define EE 100
#define HH 40

typedef unsigned long long u64;

// ---------------- f32x2 packed helpers ----------------
__device__ __forceinline__ u64 f2u2(float x, float y) {
    u64 u; asm("mov.b64 %0, {%1,%2};" : "=l"(u) : "f"(x), "f"(y)); return u;
}
__device__ __forceinline__ u64 fma2(u64 a, u64 b, u64 c) {
    u64 d; asm("fma.rn.f32x2 %0, %1, %2, %3;" : "=l"(d) : "l"(a), "l"(b), "l"(c)); return d;
}
__device__ __forceinline__ u64 add2(u64 a, u64 b) {
    u64 d; asm("add.rn.f32x2 %0, %1, %2;" : "=l"(d) : "l"(a), "l"(b)); return d;
}
__device__ __forceinline__ float2 u2f2(u64 u) {
    float lo, hi; asm("mov.b64 {%0,%1}, %2;" : "=f"(lo), "=f"(hi) : "l"(u));
    return make_float2(lo, hi);
}

// single-MUFU tanh (sm_75+)
__device__ __forceinline__ float tanhA(float x) {
    float y; asm("tanh.approx.f32 %0, %1;" : "=f"(y) : "f"(x)); return y;
}
__device__ __forceinline__ float sigA(float x) {
    return fmaf(tanhA(0.5f * x), 0.5f, 0.5f);
}

// ---------------- Device scratch ----------------
__device__ __align__(16) float g_embW0[VV * 240];
__device__ __align__(16) float g_out0[BB * TT * 80];
__device__ __align__(16) float g_gx1[(size_t)BB * TT * 240];
__device__ __align__(16) float g_Wih0T[EE * 240];
__device__ __align__(16) float g_bih0cat[240];
__device__ __align__(16) float g_Wih1T[80 * 240];
__device__ __align__(16) float g_bih1cat[240];
__device__ __align__(16) float g_Whh0P4[2 * 120 * 20 * 2];
__device__ __align__(16) float g_Whh1P4[2 * 120 * 20 * 2];
__device__ __align__(16) float g_fc1WT[320 * 128];
__device__ float g_hf0[BB * HH], g_hb0[BB * HH], g_hf1[BB * HH], g_hb1[BB * HH];
__device__ float g_avgp[BB * 80], g_maxp[BB * 80];
__device__ int g_perm[BB];
__device__ float g_sink[1024 * 32];
// pipeline state (reset by prep each launch)
__device__ int g_qhead;
__device__ int g_flagL0[BB];
__device__ int g_flagGX[BB];

// ---------------- Prep: transpose / pack all weights + reset pipeline state ----------------
__global__ void prep_weights(
    const float* __restrict__ Wih0f, const float* __restrict__ Whh0f,
    const float* __restrict__ bih0f,
    const float* __restrict__ Wih0b, const float* __restrict__ Whh0b,
    const float* __restrict__ bih0b,
    const float* __restrict__ Wih1f, const float* __restrict__ Whh1f,
    const float* __restrict__ bih1f,
    const float* __restrict__ Wih1b, const float* __restrict__ Whh1b,
    const float* __restrict__ bih1b,
    const float* __restrict__ fc1_W)
{
    int g = blockIdx.x * blockDim.x + threadIdx.x;
    int NT = gridDim.x * blockDim.x;
    if (g == 0) g_qhead = 0;
    for (int i = g; i < BB; i += NT) { g_flagL0[i] = 0; g_flagGX[i] = 0; }
    for (int i = g; i < EE * 240; i += NT) {
        int k = i / 240, j = i % 240;
        g_Wih0T[i] = (j < 120) ? Wih0f[j * EE + k] : Wih0b[(j - 120) * EE + k];
    }
    for (int i = g; i < 80 * 240; i += NT) {
        int k = i / 240, j = i % 240;
        g_Wih1T[i] = (j < 120) ? Wih1f[j * 80 + k] : Wih1b[(j - 120) * 80 + k];
    }
    for (int i = g; i < 240; i += NT) {
        g_bih0cat[i] = (i < 120) ? bih0f[i] : bih0b[i - 120];
        g_bih1cat[i] = (i < 120) ? bih1f[i] : bih1b[i - 120];
    }
    for (int i = g; i < 2 * 120 * 20 * 2; i += NT) {
        int c = i & 1;
        int t = i >> 1;
        int k2 = t % 20;
        int f = (t / 20) % 120;
        int dir = t / 2400;
        int src = f * 40 + 2 * k2 + c;
        g_Whh0P4[i] = (dir ? Whh0b : Whh0f)[src];
        g_Whh1P4[i] = (dir ? Whh1b : Whh1f)[src];
    }
    for (int i = g; i < 320 * 128; i += NT) {
        int k = i / 128, q = i % 128;
        g_fc1WT[i] = fc1_W[q * 320 + k];
    }
}

// ---------------- Length sort (descending) ----------------
__global__ void sort_kernel(const int* __restrict__ lens)
{
    __shared__ int L[BB];
    int b = threadIdx.x;
    int lb = lens[b];
    L[b] = lb;
    __syncthreads();
    int r = 0;
    #pragma unroll 8
    for (int i = 0; i < BB; i++) {
        int li = L[i];
        r += (li > lb) || (li == lb && i < b);
    }
    g_perm[r] = b;
}

// ---------------- embW GEMM ----------------
__global__ void __launch_bounds__(128) embw_kernel(const float* __restrict__ emb)
{
    int tid = threadIdx.x;
    int v0 = blockIdx.x * 32;
    int rows = VV - v0; if (rows > 32) rows = 32;
    __shared__ __align__(16) float Xt[100][36];

    const float4* xb = (const float4*)(emb + (size_t)v0 * EE);
    for (int idx = tid; idx < 32 * 25; idx += 128) {
        int r = idx / 25, c4 = idx % 25;
        float4 v = (r < rows) ? xb[r * 25 + c4] : make_float4(0.f, 0.f, 0.f, 0.f);
        Xt[4 * c4 + 0][r] = v.x;
        Xt[4 * c4 + 1][r] = v.y;
        Xt[4 * c4 + 2][r] = v.z;
        Xt[4 * c4 + 3][r] = v.w;
    }
    __syncthreads();
    if (tid >= 120) return;
    int j0 = tid, j1 = tid + 120;
    u64 a0[16], a1[16];
    {
        float b0 = g_bih0cat[j0], b1 = g_bih0cat[j1];
        u64 i0 = f2u2(b0, b0), i1 = f2u2(b1, b1);
        #pragma unroll
        for (int i = 0; i < 16; i++) { a0[i] = i0; a1[i] = i1; }
    }
    #pragma unroll 4
    for (int k = 0; k < 100; k++) {
        float w0 = g_Wih0T[k * 240 + j0];
        float w1 = g_Wih0T[k * 240 + j1];
        u64 ww0 = f2u2(w0, w0), ww1 = f2u2(w1, w1);
        const ulonglong2* ap = (const ulonglong2*)(&Xt[k][0]);
        #pragma unroll
        for (int p = 0; p < 8; p++) {
            ulonglong2 a = ap[p];
            a0[2 * p + 0] = fma2(a.x, ww0, a0[2 * p + 0]);
            a0[2 * p + 1] = fma2(a.y, ww0, a0[2 * p + 1]);
            a1[2 * p + 0] = fma2(a.x, ww1, a1[2 * p + 0]);
            a1[2 * p + 1] = fma2(a.y, ww1, a1[2 * p + 1]);
        }
    }
    float* o0 = g_embW0 + (size_t)v0 * 240 + j0;
    #pragma unroll
    for (int i = 0; i < 16; i++) {
        float2 v = u2f2(a0[i]);
        float2 u = u2f2(a1[i]);
        int r = 2 * i;
        if (r < rows)     { o0[(size_t)r * 240] = v.x;       o0[(size_t)r * 240 + 120] = u.x; }
        if (r + 1 < rows) { o0[(size_t)(r + 1) * 240] = v.y; o0[(size_t)(r + 1) * 240 + 120] = u.y; }
    }
}

// ---- shared recurrence step body ----
#define GRU_CORE(PR, PZ, PN, QR, QZ, QN, EBASE, STRIDE_EXPR, ACT_EXTRA0, ACT_EXTRA1)        \
    {                                                                                       \
        float xr = PR, xz = PZ, xn = PN, yr = QR, yz = QZ, yn = QN;                         \
        {                                                                                   \
            const float* e_ = (EBASE) + (STRIDE_EXPR);                                      \
            PR = e_[u0]; PZ = e_[40 + u0]; PN = e_[80 + u0];                                \
            QR = e_[u1c]; QZ = e_[40 + u1c]; QN = e_[80 + u1c];                             \
        }                                                                                   \
        u64 a0a = bbu[0], a0b = 0ull;                                                       \
        u64 a1a = bbu[1], a1b = 0ull;                                                       \
        u64 a2a = bbu[2], a2b = 0ull;                                                       \
        u64 a3a = bbu[3], a3b = 0ull;                                                       \
        const ulonglong2* hq = (const ulonglong2*)hsm;                                      \
        _Pragma("unroll")                                                                   \
        for (int q = 0; q < 5; q++) {                                                       \
            ulonglong2 hA = hq[2 * q], hB = hq[2 * q + 1];                                  \
            a0a = fma2(w[0][4*q],   hA.x, a0a); a0a = fma2(w[0][4*q+1], hA.y, a0a);         \
            a0b = fma2(w[0][4*q+2], hB.x, a0b); a0b = fma2(w[0][4*q+3], hB.y, a0b);         \
            a1a = fma2(w[1][4*q],   hA.x, a1a); a1a = fma2(w[1][4*q+1], hA.y, a1a);         \
            a1b = fma2(w[1][4*q+2], hB.x, a1b); a1b = fma2(w[1][4*q+3], hB.y, a1b);         \
            a2a = fma2(w[2][4*q],   hA.x, a2a); a2a = fma2(w[2][4*q+1], hA.y, a2a);         \
            a2b = fma2(w[2][4*q+2], hB.x, a2b); a2b = fma2(w[2][4*q+3], hB.y, a2b);         \
            a3a = fma2(w[3][4*q],   hA.x, a3a); a3a = fma2(w[3][4*q+1], hA.y, a3a);         \
            a3b = fma2(w[3][4*q+2], hB.x, a3b); a3b = fma2(w[3][4*q+3], hB.y, a3b);         \
        }                                                                                   \
        float2 p0 = u2f2(add2(a0a, a0b));                                                   \
        float2 p1 = u2f2(add2(a1a, a1b));                                                   \
        float2 p2 = u2f2(add2(a2a, a2b));                                                   \
        float2 p3 = u2f2(add2(a3a, a3b));                                                   \
        float d0 = p0.x + p0.y;                                                             \
        float d1 = p1.x + p1.y;                                                             \
        float d2 = p2.x + p2.y;                                                             \
        float d3 = p3.x + p3.y;                                                             \
        float s1 = __shfl_sync(FULL, d1, (lane + 8)  & 31);                                 \
        float s2 = __shfl_sync(FULL, d2, (lane + 8)  & 31);                                 \
        float s3 = __shfl_sync(FULL, d2, (lane + 16) & 31);                                 \
        float s4 = __shfl_sync(FULL, d3, (lane + 16) & 31);                                 \
        float zv0 = (lane < 24) ? s1 : s2;                                                  \
        float nv0 = (lane < 16) ? s3 : s4;                                                  \
        {                                                                                   \
            float r = sigA(xr + d0);                                                        \
            float z = sigA(xz + zv0);                                                       \
            float n = tanhA(fmaf(r, nv0, xn));                                              \
            h0 = fmaf(z, h0 - n, n);                                                        \
            hsm[u0] = h0;                                                                   \
            ACT_EXTRA0;                                                                     \
        }                                                                                   \
        {                                                                                   \
            float r = sigA(yr + d1);                                                        \
            float z = sigA(yz + s2);                                                        \
            float n = tanhA(fmaf(r, s4, yn));                                               \
            h1 = fmaf(z, h1 - n, n);                                                        \
            hsm[h1idx] = h1;                                                                \
            ACT_EXTRA1;                                                                     \
        }                                                                                   \
        __syncwarp();                                                                       \
    }

// ---------------- Fused pipeline: L0 -> gx1 (work queue) -> L1 ----------------
// 256 blocks x 128 threads, all co-resident (launch_bounds(128,2)).
// Warp wgid (0..1023) owns combo wgid: batch g_perm[wgid>>1], dir wgid&1, for BOTH L0 and L1.
__global__ void __launch_bounds__(128, 2) gru_fused(
    const int* __restrict__ text, const int* __restrict__ lens,
    const float* __restrict__ bhh0f, const float* __restrict__ bhh0b,
    const float* __restrict__ bhh1f, const float* __restrict__ bhh1b)
{
    int tid = threadIdx.x;
    int wid = tid >> 5, lane = tid & 31;
    int wgid = blockIdx.x * 4 + wid;
    __shared__ int toks_s[4][TT];
    __shared__ __align__(16) float h_s[4][80];
    __shared__ __align__(16) float Xt[80][36];
    __shared__ int curTile;
    int* toks = toks_s[wid];
    float* hsm = h_s[wid];
    const unsigned FULL = 0xffffffffu;
    float* sinkp = g_sink + (size_t)wgid * 32 + lane;

    int c = wgid;
    int b = g_perm[c >> 1];
    int dir = c & 1;
    int len = lens[b];

    int u0 = lane;
    int u1c = 32 + (lane & 7);
    bool two = (lane < 8);
    int h1idx = two ? u1c : (40 + lane);

    // ================= Phase L0 =================
    {
        for (int i = lane; i < len; i += 32) toks[i] = text[b * TT + i];

        u64 w[4][20];
        u64 bbu[4];
        const u64* wp = (const u64*)g_Whh0P4 + (size_t)dir * 120 * 20;
        const float* bhh = dir ? bhh0b : bhh0f;
        #pragma unroll
        for (int m = 0; m < 4; m++) {
            int f = lane + 32 * m;
            if (f < 120) {
                const u64* wf = wp + f * 20;
                #pragma unroll
                for (int k2 = 0; k2 < 20; k2++) w[m][k2] = wf[k2];
                bbu[m] = f2u2(bhh[f], 0.f);
            } else {
                #pragma unroll
                for (int k2 = 0; k2 < 20; k2++) w[m][k2] = 0ull;
                bbu[m] = 0ull;
            }
        }
        hsm[lane] = 0.f;
        if (lane < 16) hsm[32 + lane] = 0.f;
        __syncwarp();

        int t0 = dir ? (len - 1) : 0;
        int td = dir ? -1 : 1;
        const float* embW = g_embW0 + dir * 120;

        float Ar, Az, An, Cr, Cz, Cn, Br, Bz, Bn, Dr, Dz, Dn;
        {
            const float* e0 = embW + (size_t)toks[t0] * 240;
            Ar = e0[u0]; Az = e0[40 + u0]; An = e0[80 + u0];
            Cr = e0[u1c]; Cz = e0[40 + u1c]; Cn = e0[80 + u1c];
            int s1i = (len > 1) ? 1 : 0;
            const float* e1 = embW + (size_t)toks[t0 + s1i * td] * 240;
            Br = e1[u0]; Bz = e1[40 + u0]; Bn = e1[80 + u0];
            Dr = e1[u1c]; Dz = e1[40 + u1c]; Dn = e1[80 + u1c];
        }
        float h0 = 0.f, h1 = 0.f;
        float* outb = g_out0 + ((size_t)b * TT + t0) * 80 + dir * 40;
        long ostep = (long)td * 80;

        for (int s = 0; s < len; s += 2) {
            {
                int sp = (s + 2 < len) ? s + 2 : len - 1;
                GRU_CORE(Ar, Az, An, Cr, Cz, Cn, embW,
                         (size_t)toks[t0 + sp * td] * 240,
                         outb[u0] = h0,
                         *(two ? (outb + u1c) : sinkp) = h1)
                outb += ostep;
            }
            if (s + 1 >= len) break;
            {
                int sp = (s + 3 < len) ? s + 3 : len - 1;
                GRU_CORE(Br, Bz, Bn, Dr, Dz, Dn, embW,
                         (size_t)toks[t0 + sp * td] * 240,
                         outb[u0] = h0,
                         *(two ? (outb + u1c) : sinkp) = h1)
                outb += ostep;
            }
        }
        float* hl = dir ? g_hb0 : g_hf0;
        hl[b * HH + u0] = h0;
        if (two) hl[b * HH + u1c] = h1;

        __threadfence();
        if (lane == 0) atomicAdd(&g_flagL0[b], 1);
    }
    __syncthreads();

    // ================= Phase gx1 (block-level work queue, shortest batch first) =================
    while (true) {
        if (tid == 0) curTile = atomicAdd(&g_qhead, 1);
        __syncthreads();
        int tile = curTile;
        if (tile >= BB * 16) break;
        int rank = 511 - (tile >> 4);        // shortest first
        int chunk = tile & 15;
        int gb = g_perm[rank];
        int glen = lens[gb];
        int t0 = chunk * 32;
        if (t0 < glen) {
            if (tid == 0) {
                while (atomicAdd(&g_flagL0[gb], 0) < 2) __nanosleep(200);
            }
            __syncthreads();
            __threadfence();
            int rows = glen - t0; if (rows > 32) rows = 32;
            const float4* xb = (const float4*)(g_out0 + ((size_t)gb * TT + t0) * 80);
            for (int idx = tid; idx < 32 * 20; idx += 128) {
                int r = idx / 20, c4 = idx % 20;
                float4 v = (r < rows) ? xb[r * 20 + c4] : make_float4(0.f, 0.f, 0.f, 0.f);
                Xt[4 * c4 + 0][r] = v.x;
                Xt[4 * c4 + 1][r] = v.y;
                Xt[4 * c4 + 2][r] = v.z;
                Xt[4 * c4 + 3][r] = v.w;
            }
            __syncthreads();
            if (tid < 120) {
                int j0 = tid, j1 = tid + 120;
                u64 a0[16], a1[16];
                {
                    float b0 = g_bih1cat[j0], b1 = g_bih1cat[j1];
                    u64 i0 = f2u2(b0, b0), i1 = f2u2(b1, b1);
                    #pragma unroll
                    for (int i = 0; i < 16; i++) { a0[i] = i0; a1[i] = i1; }
                }
                #pragma unroll 4
                for (int k = 0; k < 80; k++) {
                    float w0 = g_Wih1T[k * 240 + j0];
                    float w1 = g_Wih1T[k * 240 + j1];
                    u64 ww0 = f2u2(w0, w0), ww1 = f2u2(w1, w1);
                    const ulonglong2* ap = (const ulonglong2*)(&Xt[k][0]);
                    #pragma unroll
                    for (int p = 0; p < 8; p++) {
                        ulonglong2 a = ap[p];
                        a0[2 * p + 0] = fma2(a.x, ww0, a0[2 * p + 0]);
                        a0[2 * p + 1] = fma2(a.y, ww0, a0[2 * p + 1]);
                        a1[2 * p + 0] = fma2(a.x, ww1, a1[2 * p + 0]);
                        a1[2 * p + 1] = fma2(a.y, ww1, a1[2 * p + 1]);
                    }
                }
                float* o0 = g_gx1 + ((size_t)gb * TT + t0) * 240 + j0;
                #pragma unroll
                for (int i = 0; i < 16; i++) {
                    float2 v = u2f2(a0[i]);
                    float2 u = u2f2(a1[i]);
                    int r = 2 * i;
                    if (r < rows)     { o0[(size_t)r * 240] = v.x;       o0[(size_t)r * 240 + 120] = u.x; }
                    if (r + 1 < rows) { o0[(size_t)(r + 1) * 240] = v.y; o0[(size_t)(r + 1) * 240 + 120] = u.y; }
                }
            }
            __syncthreads();
            __threadfence();
        }
        if (tid == 0) atomicAdd(&g_flagGX[gb], 1);
        __syncthreads();
    }

    // ================= Phase L1 =================
    {
        if (lane == 0) {
            while (atomicAdd(&g_flagGX[b], 0) < 16) __nanosleep(200);
        }
        __syncwarp();
        __threadfence();

        u64 w[4][20];
        u64 bbu[4];
        const u64* wp = (const u64*)g_Whh1P4 + (size_t)dir * 120 * 20;
        const float* bhh = dir ? bhh1b : bhh1f;
        #pragma unroll
        for (int m = 0; m < 4; m++) {
            int f = lane + 32 * m;
            if (f < 120) {
                const u64* wf = wp + f * 20;
                #pragma unroll
                for (int k2 = 0; k2 < 20; k2++) w[m][k2] = wf[k2];
                bbu[m] = f2u2(bhh[f], 0.f);
            } else {
                #pragma unroll
                for (int k2 = 0; k2 < 20; k2++) w[m][k2] = 0ull;
                bbu[m] = 0ull;
            }
        }
        hsm[lane] = 0.f;
        if (lane < 16) hsm[32 + lane] = 0.f;
        __syncwarp();

        int t0 = dir ? (len - 1) : 0;
        int td = dir ? -1 : 1;
        const float* gxb = g_gx1 + ((size_t)b * TT) * 240 + dir * 120;

        float Ar, Az, An, Cr, Cz, Cn, Br, Bz, Bn, Dr, Dz, Dn;
        {
            const float* e0 = gxb + (size_t)t0 * 240;
            Ar = e0[u0]; Az = e0[40 + u0]; An = e0[80 + u0];
            Cr = e0[u1c]; Cz = e0[40 + u1c]; Cn = e0[80 + u1c];
            int s1i = (len > 1) ? 1 : 0;
            const float* e1 = gxb + (size_t)(t0 + s1i * td) * 240;
            Br = e1[u0]; Bz = e1[40 + u0]; Bn = e1[80 + u0];
            Dr = e1[u1c]; Dz = e1[40 + u1c]; Dn = e1[80 + u1c];
        }
        float h0 = 0.f, h1 = 0.f;
        float sum0 = 0.f, max0 = -1e30f, sum1 = 0.f, max1 = -1e30f;

        for (int s = 0; s < len; s += 2) {
            {
                int sp = (s + 2 < len) ? s + 2 : len - 1;
                GRU_CORE(Ar, Az, An, Cr, Cz, Cn, gxb,
                         (size_t)(t0 + sp * td) * 240,
                         { sum0 += h0; max0 = fmaxf(max0, h0); },
                         { sum1 += h1; max1 = fmaxf(max1, h1); })
            }
            if (s + 1 >= len) break;
            {
                int sp = (s + 3 < len) ? s + 3 : len - 1;
                GRU_CORE(Br, Bz, Bn, Dr, Dz, Dn, gxb,
                         (size_t)(t0 + sp * td) * 240,
                         { sum0 += h0; max0 = fmaxf(max0, h0); },
                         { sum1 += h1; max1 = fmaxf(max1, h1); })
            }
        }
        float inv = __fdividef(1.f, (float)len);
        g_avgp[b * 80 + dir * 40 + u0] = sum0 * inv;
        g_maxp[b * 80 + dir * 40 + u0] = max0;
        float* hl = dir ? g_hb1 : g_hf1;
        hl[b * HH + u0] = h0;
        if (two) {
            g_avgp[b * 80 + dir * 40 + u1c] = sum1 * inv;
            g_maxp[b * 80 + dir * 40 + u1c] = max1;
            hl[b * HH + u1c] = h1;
        }
    }
}

// ---------------- Head: pool_cat -> fc1 -> leaky -> fc2 ----------------
__global__ void __launch_bounds__(128) fc_kernel(
    const float* __restrict__ fc1_b, const float* __restrict__ fc2_W,
    const float* __restrict__ fc2_b, float* __restrict__ out)
{
    int b = blockIdx.x, j = threadIdx.x;
    __shared__ float cat[320];
    for (int i = j; i < 320; i += 128) {
        float v;
        if (i < 40)       v = g_hb1[b * 40 + i];
        else if (i < 80)  v = g_hf1[b * 40 + (i - 40)];
        else if (i < 120) v = g_hb0[b * 40 + (i - 80)];
        else if (i < 160) v = g_hf0[b * 40 + (i - 120)];
        else if (i < 240) v = g_avgp[b * 80 + (i - 160)];
        else              v = g_maxp[b * 80 + (i - 240)];
        cat[i] = v;
    }
    __syncthreads();
    float acc = fc1_b[j];
    #pragma unroll 8
    for (int k = 0; k < 320; k++)
        acc = fmaf(g_fc1WT[k * 128 + j], cat[k], acc);
    float h = (acc >= 0.f) ? acc : 0.01f * acc;
    float p = h * fc2_W[j];
    #pragma unroll
    for (int o = 16; o > 0; o >>= 1) p += __shfl_down_sync(0xffffffffu, p, o);
    __shared__ float red[4];
    if ((j & 31) == 0) red[j >> 5] = p;
    __syncthreads();
    if (j == 0) out[b] = (red[0] + red[1] + red[2] + red[3]) + fc2_b[0];
}

// ---------------- Launch ----------------
extern "C" void kernel_launch(void* const* d_in, const int* in_sizes, int n_in,
                              void* d_out, int out_size)
{
    const int*   text     = (const int*)d_in[0];
    const int*   text_len = (const int*)d_in[1];
    const float* emb      = (const float*)d_in[2];
    const float* Wih0f = (const float*)d_in[3];
    const float* Whh0f = (const float*)d_in[4];
    const float* bih0f = (const float*)d_in[5];
    const float* bhh0f = (const float*)d_in[6];
    const float* Wih0b = (const float*)d_in[7];
    const float* Whh0b = (const float*)d_in[8];
    const float* bih0b = (const float*)d_in[9];
    const float* bhh0b = (const float*)d_in[10];
    const float* Wih1f = (const float*)d_in[11];
    const float* Whh1f = (const float*)d_in[12];
    const float* bih1f = (const float*)d_in[13];
    const float* bhh1f = (const float*)d_in[14];
    const float* Wih1b = (const float*)d_in[15];
    const float* Whh1b = (const float*)d_in[16];
    const float* bih1b = (const float*)d_in[17];
    const float* bhh1b = (const float*)d_in[18];
    const float* fc1_W = (const float*)d_in[19];
    const float* fc1_b = (const float*)d_in[20];
    const float* fc2_W = (const float*)d_in[21];
    const float* fc2_b = (const float*)d_in[22];
    float* out = (float*)d_out;

    prep_weights<<<160, 256>>>(Wih0f, Whh0f, bih0f, Wih0b, Whh0b, bih0b,
                               Wih1f, Whh1f, bih1f, Wih1b, Whh1b, bih1b, fc1_W);
    sort_kernel<<<1, BB>>>(text_len);
    embw_kernel<<<(VV + 31) / 32, 128>>>(emb);
    gru_fused<<<256, 128>>>(text, text_len, bhh0f, bhh0b, bhh1f, bhh1b);
    fc_kernel<<<BB, 128>>>(fc1_b, fc2_W, fc2_b, out);
}

// round 15
// speedup vs baseline: 1.3307x; 1.3307x over previous
#include <cuda_runtime.h>
#include <cuda_bf16.h>
#include <math.h>

// ---------------- Problem dims ----------------
#define BB 512
#define TT 512
#define VV 50000
#define EE 100
#define HH 40

typedef unsigned long long u64;

// ---------------- f32x2 packed helpers ----------------
__device__ __forceinline__ u64 f2u2(float x, float y) {
    u64 u; asm("mov.b64 %0, {%1,%2};" : "=l"(u) : "f"(x), "f"(y)); return u;
}
__device__ __forceinline__ u64 fma2(u64 a, u64 b, u64 c) {
    u64 d; asm("fma.rn.f32x2 %0, %1, %2, %3;" : "=l"(d) : "l"(a), "l"(b), "l"(c)); return d;
}
__device__ __forceinline__ float2 u2f2(u64 u) {
    float lo, hi; asm("mov.b64 {%0,%1}, %2;" : "=f"(lo), "=f"(hi) : "l"(u));
    return make_float2(lo, hi);
}
__device__ __forceinline__ float tanhA(float x) {
    float y; asm("tanh.approx.f32 %0, %1;" : "=f"(y) : "f"(x)); return y;
}
__device__ __forceinline__ float sigA(float x) {
    return fmaf(tanhA(0.5f * x), 0.5f, 0.5f);
}

// ---------------- Device scratch ----------------
__device__ __align__(16) float g_embW0[VV * 240];
__device__ __align__(16) float g_out0[BB * TT * 80];
__device__ __align__(16) float g_gx1[(size_t)BB * TT * 240];
__device__ __align__(16) float g_Wih0T[EE * 240];
__device__ __align__(16) float g_bih0cat[240];
__device__ __align__(16) float g_Wih1T[80 * 240];
__device__ __align__(16) float g_bih1cat[240];
__device__ __align__(16) float g_Whh0P4[2 * 120 * 20 * 2];
__device__ __align__(16) float g_Whh1P4[2 * 120 * 20 * 2];
__device__ __align__(16) float g_fc1WT[320 * 128];
__device__ float g_hf0[BB * HH], g_hb0[BB * HH], g_hf1[BB * HH], g_hb1[BB * HH];
__device__ float g_avgp[BB * 80], g_maxp[BB * 80];
__device__ int g_perm[BB];
__device__ float g_sink[512 * 32];

// ---------------- Prep ----------------
__global__ void prep_weights(
    const float* __restrict__ Wih0f, const float* __restrict__ Whh0f,
    const float* __restrict__ bih0f,
    const float* __restrict__ Wih0b, const float* __restrict__ Whh0b,
    const float* __restrict__ bih0b,
    const float* __restrict__ Wih1f, const float* __restrict__ Whh1f,
    const float* __restrict__ bih1f,
    const float* __restrict__ Wih1b, const float* __restrict__ Whh1b,
    const float* __restrict__ bih1b,
    const float* __restrict__ fc1_W)
{
    int g = blockIdx.x * blockDim.x + threadIdx.x;
    int NT = gridDim.x * blockDim.x;
    for (int i = g; i < EE * 240; i += NT) {
        int k = i / 240, j = i % 240;
        g_Wih0T[i] = (j < 120) ? Wih0f[j * EE + k] : Wih0b[(j - 120) * EE + k];
    }
    for (int i = g; i < 80 * 240; i += NT) {
        int k = i / 240, j = i % 240;
        g_Wih1T[i] = (j < 120) ? Wih1f[j * 80 + k] : Wih1b[(j - 120) * 80 + k];
    }
    for (int i = g; i < 240; i += NT) {
        g_bih0cat[i] = (i < 120) ? bih0f[i] : bih0b[i - 120];
        g_bih1cat[i] = (i < 120) ? bih1f[i] : bih1b[i - 120];
    }
    for (int i = g; i < 2 * 120 * 20 * 2; i += NT) {
        int c = i & 1;
        int t = i >> 1;
        int k2 = t % 20;
        int f = (t / 20) % 120;
        int dir = t / 2400;
        int src = f * 40 + 2 * k2 + c;
        g_Whh0P4[i] = (dir ? Whh0b : Whh0f)[src];
        g_Whh1P4[i] = (dir ? Whh1b : Whh1f)[src];
    }
    for (int i = g; i < 320 * 128; i += NT) {
        int k = i / 128, q = i % 128;
        g_fc1WT[i] = fc1_W[q * 320 + k];
    }
}

// ---------------- Length sort (descending) ----------------
__global__ void sort_kernel(const int* __restrict__ lens)
{
    __shared__ int L[BB];
    int b = threadIdx.x;
    int lb = lens[b];
    L[b] = lb;
    __syncthreads();
    int r = 0;
    #pragma unroll 8
    for (int i = 0; i < BB; i++) {
        int li = L[i];
        r += (li > lb) || (li == lb && i < b);
    }
    g_perm[r] = b;
}

// ---------------- embW GEMM ----------------
__global__ void __launch_bounds__(128) embw_kernel(const float* __restrict__ emb)
{
    int tid = threadIdx.x;
    int v0 = blockIdx.x * 32;
    int rows = VV - v0; if (rows > 32) rows = 32;
    __shared__ __align__(16) float Xt[100][36];

    const float4* xb = (const float4*)(emb + (size_t)v0 * EE);
    for (int idx = tid; idx < 32 * 25; idx += 128) {
        int r = idx / 25, c4 = idx % 25;
        float4 v = (r < rows) ? xb[r * 25 + c4] : make_float4(0.f, 0.f, 0.f, 0.f);
        Xt[4 * c4 + 0][r] = v.x;
        Xt[4 * c4 + 1][r] = v.y;
        Xt[4 * c4 + 2][r] = v.z;
        Xt[4 * c4 + 3][r] = v.w;
    }
    __syncthreads();
    if (tid >= 120) return;
    int j0 = tid, j1 = tid + 120;
    u64 a0[16], a1[16];
    {
        float b0 = g_bih0cat[j0], b1 = g_bih0cat[j1];
        u64 i0 = f2u2(b0, b0), i1 = f2u2(b1, b1);
        #pragma unroll
        for (int i = 0; i < 16; i++) { a0[i] = i0; a1[i] = i1; }
    }
    #pragma unroll 4
    for (int k = 0; k < 100; k++) {
        float w0 = g_Wih0T[k * 240 + j0];
        float w1 = g_Wih0T[k * 240 + j1];
        u64 ww0 = f2u2(w0, w0), ww1 = f2u2(w1, w1);
        const ulonglong2* ap = (const ulonglong2*)(&Xt[k][0]);
        #pragma unroll
        for (int p = 0; p < 8; p++) {
            ulonglong2 a = ap[p];
            a0[2 * p + 0] = fma2(a.x, ww0, a0[2 * p + 0]);
            a0[2 * p + 1] = fma2(a.y, ww0, a0[2 * p + 1]);
            a1[2 * p + 0] = fma2(a.x, ww1, a1[2 * p + 0]);
            a1[2 * p + 1] = fma2(a.y, ww1, a1[2 * p + 1]);
        }
    }
    float* o0 = g_embW0 + (size_t)v0 * 240 + j0;
    #pragma unroll
    for (int i = 0; i < 16; i++) {
        float2 v = u2f2(a0[i]);
        float2 u = u2f2(a1[i]);
        int r = 2 * i;
        if (r < rows)     { o0[(size_t)r * 240] = v.x;       o0[(size_t)r * 240 + 120] = u.x; }
        if (r + 1 < rows) { o0[(size_t)(r + 1) * 240] = v.y; o0[(size_t)(r + 1) * 240 + 120] = u.y; }
    }
}

// ---------------- gx1 GEMM ----------------
__global__ void __launch_bounds__(128) gx1_kernel(const int* __restrict__ lens)
{
    int b = blockIdx.x;
    int t0 = blockIdx.y * 32;
    int len = lens[b];
    if (t0 >= len) return;
    int rows = len - t0; if (rows > 32) rows = 32;
    int tid = threadIdx.x;
    __shared__ __align__(16) float Xt[80][36];

    const float4* xb = (const float4*)(g_out0 + ((size_t)b * TT + t0) * 80);
    for (int idx = tid; idx < 32 * 20; idx += 128) {
        int r = idx / 20, c4 = idx % 20;
        float4 v = (r < rows) ? xb[r * 20 + c4] : make_float4(0.f, 0.f, 0.f, 0.f);
        Xt[4 * c4 + 0][r] = v.x;
        Xt[4 * c4 + 1][r] = v.y;
        Xt[4 * c4 + 2][r] = v.z;
        Xt[4 * c4 + 3][r] = v.w;
    }
    __syncthreads();
    if (tid >= 120) return;
    int j0 = tid, j1 = tid + 120;
    u64 a0[16], a1[16];
    {
        float b0 = g_bih1cat[j0], b1 = g_bih1cat[j1];
        u64 i0 = f2u2(b0, b0), i1 = f2u2(b1, b1);
        #pragma unroll
        for (int i = 0; i < 16; i++) { a0[i] = i0; a1[i] = i1; }
    }
    #pragma unroll 4
    for (int k = 0; k < 80; k++) {
        float w0 = g_Wih1T[k * 240 + j0];
        float w1 = g_Wih1T[k * 240 + j1];
        u64 ww0 = f2u2(w0, w0), ww1 = f2u2(w1, w1);
        const ulonglong2* ap = (const ulonglong2*)(&Xt[k][0]);
        #pragma unroll
        for (int p = 0; p < 8; p++) {
            ulonglong2 a = ap[p];
            a0[2 * p + 0] = fma2(a.x, ww0, a0[2 * p + 0]);
            a0[2 * p + 1] = fma2(a.y, ww0, a0[2 * p + 1]);
            a1[2 * p + 0] = fma2(a.x, ww1, a1[2 * p + 0]);
            a1[2 * p + 1] = fma2(a.y, ww1, a1[2 * p + 1]);
        }
    }
    float* o0 = g_gx1 + ((size_t)b * TT + t0) * 240 + j0;
    #pragma unroll
    for (int i = 0; i < 16; i++) {
        float2 v = u2f2(a0[i]);
        float2 u = u2f2(a1[i]);
        int r = 2 * i;
        if (r < rows)     { o0[(size_t)r * 240] = v.x;       o0[(size_t)r * 240 + 120] = u.x; }
        if (r + 1 < rows) { o0[(size_t)(r + 1) * 240] = v.y; o0[(size_t)(r + 1) * 240 + 120] = u.y; }
    }
}

// ---- dot: 4 gate rows for one batch from its h smem ----
#define DOT4(HSMX, D0, D1, D2, D3)                                                  \
    float D0, D1, D2, D3;                                                           \
    {                                                                               \
        u64 ac0 = bbu[0], ac1 = bbu[1], ac2 = bbu[2], ac3 = bbu[3];                 \
        const ulonglong2* hq = (const ulonglong2*)(HSMX);                           \
        _Pragma("unroll")                                                           \
        for (int q = 0; q < 10; q++) {                                              \
            ulonglong2 hv = hq[q];                                                  \
            ac0 = fma2(w[0][2*q], hv.x, ac0); ac0 = fma2(w[0][2*q+1], hv.y, ac0);   \
            ac1 = fma2(w[1][2*q], hv.x, ac1); ac1 = fma2(w[1][2*q+1], hv.y, ac1);   \
            ac2 = fma2(w[2][2*q], hv.x, ac2); ac2 = fma2(w[2][2*q+1], hv.y, ac2);   \
            ac3 = fma2(w[3][2*q], hv.x, ac3); ac3 = fma2(w[3][2*q+1], hv.y, ac3);   \
        }                                                                           \
        float2 p0 = u2f2(ac0), p1 = u2f2(ac1), p2 = u2f2(ac2), p3 = u2f2(ac3);      \
        D0 = p0.x + p0.y; D1 = p1.x + p1.y; D2 = p2.x + p2.y; D3 = p3.x + p3.y;     \
    }

// ---- one sub-step for one batch (layer0 variant: stores to g_out0) ----
#define PBATCH_L0(GR0,GZ0,GN0,GR1,GZ1,GN1, HSMX, H0,H1, TOKSX, T0X, LENX, OUTBX, SCUR) \
    {                                                                               \
        float xr=GR0, xz=GZ0, xn=GN0, yr=GR1, yz=GZ1, yn=GN1;                       \
        { int sp_ = (SCUR) + 2; sp_ = (sp_ < (LENX)) ? sp_ : ((LENX) - 1);          \
          const float* e_ = embW + (size_t)TOKSX[(T0X) + sp_ * td] * 240;           \
          GR0 = e_[u0]; GZ0 = e_[40 + u0]; GN0 = e_[80 + u0];                       \
          GR1 = e_[u1c]; GZ1 = e_[40 + u1c]; GN1 = e_[80 + u1c]; }                  \
        DOT4(HSMX, d0, d1, d2, d3)                                                  \
        float s1 = __shfl_sync(FULL, d1, (lane + 8)  & 31);                         \
        float s2 = __shfl_sync(FULL, d2, (lane + 8)  & 31);                         \
        float s3 = __shfl_sync(FULL, d2, (lane + 16) & 31);                         \
        float s4 = __shfl_sync(FULL, d3, (lane + 16) & 31);                         \
        float zv0 = (lane < 24) ? s1 : s2;                                          \
        float nv0 = (lane < 16) ? s3 : s4;                                          \
        bool alive = ((SCUR) < (LENX));                                             \
        { float r = sigA(xr + d0); float z = sigA(xz + zv0);                        \
          float n = tanhA(fmaf(r, nv0, xn));                                        \
          float hn = fmaf(z, H0 - n, n); H0 = alive ? hn : H0;                      \
          HSMX[u0] = H0; *(alive ? (OUTBX + u0) : sinkp) = H0; }                    \
        { float r = sigA(yr + d1); float z = sigA(yz + s2);                         \
          float n = tanhA(fmaf(r, s4, yn));                                         \
          float hn = fmaf(z, H1 - n, n); H1 = alive ? hn : H1;                      \
          HSMX[h1idx] = H1; *((alive && two) ? (OUTBX + u1c) : sinkp) = H1; }       \
        OUTBX += ostep;                                                             \
    }

// ---- one sub-step for one batch (layer1 variant: fused pooling) ----
#define PBATCH_L1(GR0,GZ0,GN0,GR1,GZ1,GN1, HSMX, H0,H1, GXBX, T0X, LENX, SUM0,MAX0,SUM1,MAX1, SCUR) \
    {                                                                               \
        float xr=GR0, xz=GZ0, xn=GN0, yr=GR1, yz=GZ1, yn=GN1;                       \
        { int sp_ = (SCUR) + 2; sp_ = (sp_ < (LENX)) ? sp_ : ((LENX) - 1);          \
          const float* e_ = GXBX + (size_t)((T0X) + sp_ * td) * 240;                \
          GR0 = e_[u0]; GZ0 = e_[40 + u0]; GN0 = e_[80 + u0];                       \
          GR1 = e_[u1c]; GZ1 = e_[40 + u1c]; GN1 = e_[80 + u1c]; }                  \
        DOT4(HSMX, d0, d1, d2, d3)                                                  \
        float s1 = __shfl_sync(FULL, d1, (lane + 8)  & 31);                         \
        float s2 = __shfl_sync(FULL, d2, (lane + 8)  & 31);                         \
        float s3 = __shfl_sync(FULL, d2, (lane + 16) & 31);                         \
        float s4 = __shfl_sync(FULL, d3, (lane + 16) & 31);                         \
        float zv0 = (lane < 24) ? s1 : s2;                                          \
        float nv0 = (lane < 16) ? s3 : s4;                                          \
        bool alive = ((SCUR) < (LENX));                                             \
        { float r = sigA(xr + d0); float z = sigA(xz + zv0);                        \
          float n = tanhA(fmaf(r, nv0, xn));                                        \
          float hn = fmaf(z, H0 - n, n); H0 = alive ? hn : H0;                      \
          HSMX[u0] = H0;                                                            \
          SUM0 += alive ? H0 : 0.f; MAX0 = fmaxf(MAX0, H0); }                       \
        { float r = sigA(yr + d1); float z = sigA(yz + s2);                         \
          float n = tanhA(fmaf(r, s4, yn));                                         \
          float hn = fmaf(z, H1 - n, n); H1 = alive ? hn : H1;                      \
          HSMX[h1idx] = H1;                                                         \
          SUM1 += alive ? H1 : 0.f; MAX1 = fmaxf(MAX1, H1); }                       \
    }

// ---------------- Layer 0: one warp runs TWO batches (same dir) interleaved ----------------
// warp w (0..511): dir = w&1, pair = w>>1; batches perm[2*pair], perm[2*pair+1] (adjacent lens)
__global__ void __launch_bounds__(128) gru_layer0(
    const int* __restrict__ text, const int* __restrict__ lens,
    const float* __restrict__ bhh0f, const float* __restrict__ bhh0b)
{
    int wid = threadIdx.x >> 5, lane = threadIdx.x & 31;
    int wgid = blockIdx.x * 4 + wid;
    __shared__ int toks_s[4][2][TT];
    __shared__ __align__(16) float h_s[4][160];
    const unsigned FULL = 0xffffffffu;
    float* sinkp = g_sink + (size_t)wgid * 32 + lane;

    int dir = wgid & 1;
    int pi = wgid >> 1;
    int bA = g_perm[2 * pi], bB = g_perm[2 * pi + 1];
    int lenA = lens[bA], lenB = lens[bB];
    int len = lenA;                    // lenA >= lenB (sorted desc)
    int* toksA = toks_s[wid][0];
    int* toksB = toks_s[wid][1];
    float* hsmA = h_s[wid];
    float* hsmB = h_s[wid] + 80;

    for (int i = lane; i < lenA; i += 32) toksA[i] = text[bA * TT + i];
    for (int i = lane; i < lenB; i += 32) toksB[i] = text[bB * TT + i];

    u64 w[4][20];
    u64 bbu[4];
    {
        const u64* wp = (const u64*)g_Whh0P4 + (size_t)dir * 120 * 20;
        const float* bhh = dir ? bhh0b : bhh0f;
        #pragma unroll
        for (int m = 0; m < 4; m++) {
            int f = lane + 32 * m;
            if (f < 120) {
                const u64* wf = wp + f * 20;
                #pragma unroll
                for (int k2 = 0; k2 < 20; k2++) w[m][k2] = wf[k2];
                bbu[m] = f2u2(bhh[f], 0.f);
            } else {
                #pragma unroll
                for (int k2 = 0; k2 < 20; k2++) w[m][k2] = 0ull;
                bbu[m] = 0ull;
            }
        }
    }
    hsmA[lane] = 0.f; hsmB[lane] = 0.f;
    if (lane < 8) { hsmA[32 + lane] = 0.f; hsmB[32 + lane] = 0.f; }
    __syncwarp();

    int td = dir ? -1 : 1;
    int t0A = dir ? (lenA - 1) : 0;
    int t0B = dir ? (lenB - 1) : 0;
    const float* embW = g_embW0 + dir * 120;
    int u0 = lane;
    int u1c = 32 + (lane & 7);
    bool two = (lane < 8);
    int h1idx = two ? u1c : (40 + lane);

    // gate buffers: [batch][parity] x {r,z,n for u0,u1}
    float Aer, Aez, Aen, Aer1, Aez1, Aen1, Aor, Aoz, Aon, Aor1, Aoz1, Aon1;
    float Ber, Bez, Ben, Ber1, Bez1, Ben1, Bor, Boz, Bon, Bor1, Boz1, Bon1;
    {
        const float* e = embW + (size_t)toksA[t0A] * 240;
        Aer = e[u0]; Aez = e[40 + u0]; Aen = e[80 + u0];
        Aer1 = e[u1c]; Aez1 = e[40 + u1c]; Aen1 = e[80 + u1c];
        int s1A = (lenA > 1) ? 1 : 0;
        const float* e2 = embW + (size_t)toksA[t0A + s1A * td] * 240;
        Aor = e2[u0]; Aoz = e2[40 + u0]; Aon = e2[80 + u0];
        Aor1 = e2[u1c]; Aoz1 = e2[40 + u1c]; Aon1 = e2[80 + u1c];
        const float* f = embW + (size_t)toksB[t0B] * 240;
        Ber = f[u0]; Bez = f[40 + u0]; Ben = f[80 + u0];
        Ber1 = f[u1c]; Bez1 = f[40 + u1c]; Ben1 = f[80 + u1c];
        int s1B = (lenB > 1) ? 1 : 0;
        const float* f2 = embW + (size_t)toksB[t0B + s1B * td] * 240;
        Bor = f2[u0]; Boz = f2[40 + u0]; Bon = f2[80 + u0];
        Bor1 = f2[u1c]; Boz1 = f2[40 + u1c]; Bon1 = f2[80 + u1c];
    }
    float hA0 = 0.f, hA1 = 0.f, hB0 = 0.f, hB1 = 0.f;
    float* outbA = g_out0 + ((size_t)bA * TT + t0A) * 80 + dir * 40;
    float* outbB = g_out0 + ((size_t)bB * TT + t0B) * 80 + dir * 40;
    long ostep = (long)td * 80;

    for (int s = 0; s < len; s += 2) {
        PBATCH_L0(Aer, Aez, Aen, Aer1, Aez1, Aen1, hsmA, hA0, hA1, toksA, t0A, lenA, outbA, s)
        PBATCH_L0(Ber, Bez, Ben, Ber1, Bez1, Ben1, hsmB, hB0, hB1, toksB, t0B, lenB, outbB, s)
        __syncwarp();
        if (s + 1 >= len) break;
        PBATCH_L0(Aor, Aoz, Aon, Aor1, Aoz1, Aon1, hsmA, hA0, hA1, toksA, t0A, lenA, outbA, s + 1)
        PBATCH_L0(Bor, Boz, Bon, Bor1, Boz1, Bon1, hsmB, hB0, hB1, toksB, t0B, lenB, outbB, s + 1)
        __syncwarp();
    }
    float* hl = dir ? g_hb0 : g_hf0;
    hl[bA * HH + u0] = hA0;
    hl[bB * HH + u0] = hB0;
    if (two) { hl[bA * HH + u1c] = hA1; hl[bB * HH + u1c] = hB1; }
}

// ---------------- Layer 1: paired batches, gx precomputed, fused pooling ----------------
__global__ void __launch_bounds__(128) gru_layer1(
    const int* __restrict__ lens,
    const float* __restrict__ bhh1f, const float* __restrict__ bhh1b)
{
    int wid = threadIdx.x >> 5, lane = threadIdx.x & 31;
    int wgid = blockIdx.x * 4 + wid;
    __shared__ __align__(16) float h_s[4][160];
    const unsigned FULL = 0xffffffffu;

    int dir = wgid & 1;
    int pi = wgid >> 1;
    int bA = g_perm[2 * pi], bB = g_perm[2 * pi + 1];
    int lenA = lens[bA], lenB = lens[bB];
    int len = lenA;
    float* hsmA = h_s[wid];
    float* hsmB = h_s[wid] + 80;

    u64 w[4][20];
    u64 bbu[4];
    {
        const u64* wp = (const u64*)g_Whh1P4 + (size_t)dir * 120 * 20;
        const float* bhh = dir ? bhh1b : bhh1f;
        #pragma unroll
        for (int m = 0; m < 4; m++) {
            int f = lane + 32 * m;
            if (f < 120) {
                const u64* wf = wp + f * 20;
                #pragma unroll
                for (int k2 = 0; k2 < 20; k2++) w[m][k2] = wf[k2];
                bbu[m] = f2u2(bhh[f], 0.f);
            } else {
                #pragma unroll
                for (int k2 = 0; k2 < 20; k2++) w[m][k2] = 0ull;
                bbu[m] = 0ull;
            }
        }
    }
    hsmA[lane] = 0.f; hsmB[lane] = 0.f;
    if (lane < 8) { hsmA[32 + lane] = 0.f; hsmB[32 + lane] = 0.f; }
    __syncwarp();

    int td = dir ? -1 : 1;
    int t0A = dir ? (lenA - 1) : 0;
    int t0B = dir ? (lenB - 1) : 0;
    const float* gxbA = g_gx1 + ((size_t)bA * TT) * 240 + dir * 120;
    const float* gxbB = g_gx1 + ((size_t)bB * TT) * 240 + dir * 120;
    int u0 = lane;
    int u1c = 32 + (lane & 7);
    bool two = (lane < 8);
    int h1idx = two ? u1c : (40 + lane);

    float Aer, Aez, Aen, Aer1, Aez1, Aen1, Aor, Aoz, Aon, Aor1, Aoz1, Aon1;
    float Ber, Bez, Ben, Ber1, Bez1, Ben1, Bor, Boz, Bon, Bor1, Boz1, Bon1;
    {
        const float* e = gxbA + (size_t)t0A * 240;
        Aer = e[u0]; Aez = e[40 + u0]; Aen = e[80 + u0];
        Aer1 = e[u1c]; Aez1 = e[40 + u1c]; Aen1 = e[80 + u1c];
        int s1A = (lenA > 1) ? 1 : 0;
        const float* e2 = gxbA + (size_t)(t0A + s1A * td) * 240;
        Aor = e2[u0]; Aoz = e2[40 + u0]; Aon = e2[80 + u0];
        Aor1 = e2[u1c]; Aoz1 = e2[40 + u1c]; Aon1 = e2[80 + u1c];
        const float* f = gxbB + (size_t)t0B * 240;
        Ber = f[u0]; Bez = f[40 + u0]; Ben = f[80 + u0];
        Ber1 = f[u1c]; Bez1 = f[40 + u1c]; Ben1 = f[80 + u1c];
        int s1B = (lenB > 1) ? 1 : 0;
        const float* f2 = gxbB + (size_t)(t0B + s1B * td) * 240;
        Bor = f2[u0]; Boz = f2[40 + u0]; Bon = f2[80 + u0];
        Bor1 = f2[u1c]; Boz1 = f2[40 + u1c]; Bon1 = f2[80 + u1c];
    }
    float hA0 = 0.f, hA1 = 0.f, hB0 = 0.f, hB1 = 0.f;
    float sA0 = 0.f, mA0 = -1e30f, sA1 = 0.f, mA1 = -1e30f;
    float sB0 = 0.f, mB0 = -1e30f, sB1 = 0.f, mB1 = -1e30f;

    for (int s = 0; s < len; s += 2) {
        PBATCH_L1(Aer, Aez, Aen, Aer1, Aez1, Aen1, hsmA, hA0, hA1, gxbA, t0A, lenA, sA0, mA0, sA1, mA1, s)
        PBATCH_L1(Ber, Bez, Ben, Ber1, Bez1, Ben1, hsmB, hB0, hB1, gxbB, t0B, lenB, sB0, mB0, sB1, mB1, s)
        __syncwarp();
        if (s + 1 >= len) break;
        PBATCH_L1(Aor, Aoz, Aon, Aor1, Aoz1, Aon1, hsmA, hA0, hA1, gxbA, t0A, lenA, sA0, mA0, sA1, mA1, s + 1)
        PBATCH_L1(Bor, Boz, Bon, Bor1, Boz1, Bon1, hsmB, hB0, hB1, gxbB, t0B, lenB, sB0, mB0, sB1, mB1, s + 1)
        __syncwarp();
    }
    float invA = __fdividef(1.f, (float)lenA);
    float invB = __fdividef(1.f, (float)lenB);
    float* hl = dir ? g_hb1 : g_hf1;
    g_avgp[bA * 80 + dir * 40 + u0] = sA0 * invA;
    g_maxp[bA * 80 + dir * 40 + u0] = mA0;
    g_avgp[bB * 80 + dir * 40 + u0] = sB0 * invB;
    g_maxp[bB * 80 + dir * 40 + u0] = mB0;
    hl[bA * HH + u0] = hA0;
    hl[bB * HH + u0] = hB0;
    if (two) {
        g_avgp[bA * 80 + dir * 40 + u1c] = sA1 * invA;
        g_maxp[bA * 80 + dir * 40 + u1c] = mA1;
        g_avgp[bB * 80 + dir * 40 + u1c] = sB1 * invB;
        g_maxp[bB * 80 + dir * 40 + u1c] = mB1;
        hl[bA * HH + u1c] = hA1;
        hl[bB * HH + u1c] = hB1;
    }
}

// ---------------- Head ----------------
__global__ void __launch_bounds__(128) fc_kernel(
    const float* __restrict__ fc1_b, const float* __restrict__ fc2_W,
    const float* __restrict__ fc2_b, float* __restrict__ out)
{
    int b = blockIdx.x, j = threadIdx.x;
    __shared__ float cat[320];
    for (int i = j; i < 320; i += 128) {
        float v;
        if (i < 40)       v = g_hb1[b * 40 + i];
        else if (i < 80)  v = g_hf1[b * 40 + (i - 40)];
        else if (i < 120) v = g_hb0[b * 40 + (i - 80)];
        else if (i < 160) v = g_hf0[b * 40 + (i - 120)];
        else if (i < 240) v = g_avgp[b * 80 + (i - 160)];
        else              v = g_maxp[b * 80 + (i - 240)];
        cat[i] = v;
    }
    __syncthreads();
    float acc = fc1_b[j];
    #pragma unroll 8
    for (int k = 0; k < 320; k++)
        acc = fmaf(g_fc1WT[k * 128 + j], cat[k], acc);
    float h = (acc >= 0.f) ? acc : 0.01f * acc;
    float p = h * fc2_W[j];
    #pragma unroll
    for (int o = 16; o > 0; o >>= 1) p += __shfl_down_sync(0xffffffffu, p, o);
    __shared__ float red[4];
    if ((j & 31) == 0) red[j >> 5] = p;
    __syncthreads();
    if (j == 0) out[b] = (red[0] + red[1] + red[2] + red[3]) + fc2_b[0];
}

// ---------------- Launch ----------------
extern "C" void kernel_launch(void* const* d_in, const int* in_sizes, int n_in,
                              void* d_out, int out_size)
{
    const int*   text     = (const int*)d_in[0];
    const int*   text_len = (const int*)d_in[1];
    const float* emb      = (const float*)d_in[2];
    const float* Wih0f = (const float*)d_in[3];
    const float* Whh0f = (const float*)d_in[4];
    const float* bih0f = (const float*)d_in[5];
    const float* bhh0f = (const float*)d_in[6];
    const float* Wih0b = (const float*)d_in[7];
    const float* Whh0b = (const float*)d_in[8];
    const float* bih0b = (const float*)d_in[9];
    const float* bhh0b = (const float*)d_in[10];
    const float* Wih1f = (const float*)d_in[11];
    const float* Whh1f = (const float*)d_in[12];
    const float* bih1f = (const float*)d_in[13];
    const float* bhh1f = (const float*)d_in[14];
    const float* Wih1b = (const float*)d_in[15];
    const float* Whh1b = (const float*)d_in[16];
    const float* bih1b = (const float*)d_in[17];
    const float* bhh1b = (const float*)d_in[18];
    const float* fc1_W = (const float*)d_in[19];
    const float* fc1_b = (const float*)d_in[20];
    const float* fc2_W = (const float*)d_in[21];
    const float* fc2_b = (const float*)d_in[22];
    float* out = (float*)d_out;

    prep_weights<<<160, 256>>>(Wih0f, Whh0f, bih0f, Wih0b, Whh0b, bih0b,
                               Wih1f, Whh1f, bih1f, Wih1b, Whh1b, bih1b, fc1_W);
    sort_kernel<<<1, BB>>>(text_len);
    embw_kernel<<<(VV + 31) / 32, 128>>>(emb);
    gru_layer0<<<128, 128>>>(text, text_len, bhh0f, bhh0b);
    gx1_kernel<<<dim3(BB, TT / 32), 128>>>(text_len);
    gru_layer1<<<128, 128>>>(text_len, bhh1f, bhh1b);
    fc_kernel<<<BB, 128>>>(fc1_b, fc2_W, fc2_b, out);
}

// round 16
// speedup vs baseline: 1.8098x; 1.3601x over previous
#include <cuda_runtime.h>
#include <cuda_bf16.h>
#include <math.h>

// ---------------- Problem dims ----------------
#define BB 512
#define TT 512
#define VV 50000
#define EE 100
#define HH 40

typedef unsigned long long u64;

// ---------------- f32x2 packed helpers ----------------
__device__ __forceinline__ u64 f2u2(float x, float y) {
    u64 u; asm("mov.b64 %0, {%1,%2};" : "=l"(u) : "f"(x), "f"(y)); return u;
}
__device__ __forceinline__ u64 fma2(u64 a, u64 b, u64 c) {
    u64 d; asm("fma.rn.f32x2 %0, %1, %2, %3;" : "=l"(d) : "l"(a), "l"(b), "l"(c)); return d;
}
__device__ __forceinline__ u64 add2(u64 a, u64 b) {
    u64 d; asm("add.rn.f32x2 %0, %1, %2;" : "=l"(d) : "l"(a), "l"(b)); return d;
}
__device__ __forceinline__ float2 u2f2(u64 u) {
    float lo, hi; asm("mov.b64 {%0,%1}, %2;" : "=f"(lo), "=f"(hi) : "l"(u));
    return make_float2(lo, hi);
}

// single-MUFU tanh (sm_75+)
__device__ __forceinline__ float tanhA(float x) {
    float y; asm("tanh.approx.f32 %0, %1;" : "=f"(y) : "f"(x)); return y;
}
__device__ __forceinline__ float sigA(float x) {
    return fmaf(tanhA(0.5f * x), 0.5f, 0.5f);
}

// ---------------- Device scratch ----------------
// rz-paired rows: each 240-float row = [dir0: rz pairs (80) | n (40)][dir1: same]
__device__ __align__(16) float g_embW0[VV * 240];
__device__ __align__(16) float g_out0[BB * TT * 80];
__device__ __align__(16) float g_gx1[(size_t)BB * TT * 240];
__device__ __align__(16) float g_Wih0T[EE * 240];
__device__ __align__(16) float g_bih0cat[240];
__device__ __align__(16) float g_Wih1T[80 * 240];
__device__ __align__(16) float g_bih1cat[240];
// 4-output gate-owner pack: [dir][f(0..119)][k2(0..19)] u64 pairs
__device__ __align__(16) float g_Whh0P4[2 * 120 * 20 * 2];
__device__ __align__(16) float g_Whh1P4[2 * 120 * 20 * 2];
__device__ __align__(16) float g_fc1WT[320 * 128];
__device__ float g_hf0[BB * HH], g_hb0[BB * HH], g_hf1[BB * HH], g_hb1[BB * HH];
__device__ float g_avgp[BB * 80], g_maxp[BB * 80];
__device__ int g_perm[BB];
__device__ float g_sink[592 * 32];

// ---------------- Prep ----------------
__global__ void prep_weights(
    const float* __restrict__ Wih0f, const float* __restrict__ Whh0f,
    const float* __restrict__ bih0f,
    const float* __restrict__ Wih0b, const float* __restrict__ Whh0b,
    const float* __restrict__ bih0b,
    const float* __restrict__ Wih1f, const float* __restrict__ Whh1f,
    const float* __restrict__ bih1f,
    const float* __restrict__ Wih1b, const float* __restrict__ Whh1b,
    const float* __restrict__ bih1b,
    const float* __restrict__ fc1_W)
{
    int g = blockIdx.x * blockDim.x + threadIdx.x;
    int NT = gridDim.x * blockDim.x;
    for (int i = g; i < EE * 240; i += NT) {
        int k = i / 240, j = i % 240;
        g_Wih0T[i] = (j < 120) ? Wih0f[j * EE + k] : Wih0b[(j - 120) * EE + k];
    }
    for (int i = g; i < 80 * 240; i += NT) {
        int k = i / 240, j = i % 240;
        g_Wih1T[i] = (j < 120) ? Wih1f[j * 80 + k] : Wih1b[(j - 120) * 80 + k];
    }
    for (int i = g; i < 240; i += NT) {
        g_bih0cat[i] = (i < 120) ? bih0f[i] : bih0b[i - 120];
        g_bih1cat[i] = (i < 120) ? bih1f[i] : bih1b[i - 120];
    }
    for (int i = g; i < 2 * 120 * 20 * 2; i += NT) {
        int c = i & 1;
        int t = i >> 1;
        int k2 = t % 20;
        int f = (t / 20) % 120;
        int dir = t / 2400;
        int src = f * 40 + 2 * k2 + c;
        g_Whh0P4[i] = (dir ? Whh0b : Whh0f)[src];
        g_Whh1P4[i] = (dir ? Whh1b : Whh1f)[src];
    }
    for (int i = g; i < 320 * 128; i += NT) {
        int k = i / 128, q = i % 128;
        g_fc1WT[i] = fc1_W[q * 320 + k];
    }
}

// ---------------- Length sort (descending) ----------------
__global__ void sort_kernel(const int* __restrict__ lens)
{
    __shared__ int L[BB];
    int b = threadIdx.x;
    int lb = lens[b];
    L[b] = lb;
    __syncthreads();
    int r = 0;
    #pragma unroll 8
    for (int i = 0; i < BB; i++) {
        int li = L[i];
        r += (li > lb) || (li == lb && i < b);
    }
    g_perm[r] = b;
}

// column remap for rz-paired layout: within-dir index jj (=gate*40+u) -> new offset
__device__ __forceinline__ int rz_off(int jj) {
    int gate = jj / 40, u = jj % 40;
    return (gate < 2) ? (2 * u + gate) : (80 + u);
}

// ---------------- embW GEMM: [50000,100] x [100,240] + bias; rz-paired stores ----------------
__global__ void __launch_bounds__(128) embw_kernel(const float* __restrict__ emb)
{
    int tid = threadIdx.x;
    int v0 = blockIdx.x * 32;
    int rows = VV - v0; if (rows > 32) rows = 32;
    __shared__ __align__(16) float Xt[100][36];

    const float4* xb = (const float4*)(emb + (size_t)v0 * EE);
    for (int idx = tid; idx < 32 * 25; idx += 128) {
        int r = idx / 25, c4 = idx % 25;
        float4 v = (r < rows) ? xb[r * 25 + c4] : make_float4(0.f, 0.f, 0.f, 0.f);
        Xt[4 * c4 + 0][r] = v.x;
        Xt[4 * c4 + 1][r] = v.y;
        Xt[4 * c4 + 2][r] = v.z;
        Xt[4 * c4 + 3][r] = v.w;
    }
    __syncthreads();
    if (tid >= 120) return;
    int j0 = tid, j1 = tid + 120;
    u64 a0[16], a1[16];
    {
        float b0 = g_bih0cat[j0], b1 = g_bih0cat[j1];
        u64 i0 = f2u2(b0, b0), i1 = f2u2(b1, b1);
        #pragma unroll
        for (int i = 0; i < 16; i++) { a0[i] = i0; a1[i] = i1; }
    }
    #pragma unroll 4
    for (int k = 0; k < 100; k++) {
        float w0 = g_Wih0T[k * 240 + j0];
        float w1 = g_Wih0T[k * 240 + j1];
        u64 ww0 = f2u2(w0, w0), ww1 = f2u2(w1, w1);
        const ulonglong2* ap = (const ulonglong2*)(&Xt[k][0]);
        #pragma unroll
        for (int p = 0; p < 8; p++) {
            ulonglong2 a = ap[p];
            a0[2 * p + 0] = fma2(a.x, ww0, a0[2 * p + 0]);
            a0[2 * p + 1] = fma2(a.y, ww0, a0[2 * p + 1]);
            a1[2 * p + 0] = fma2(a.x, ww1, a1[2 * p + 0]);
            a1[2 * p + 1] = fma2(a.y, ww1, a1[2 * p + 1]);
        }
    }
    int noff = rz_off(tid);
    float* o0 = g_embW0 + (size_t)v0 * 240 + noff;
    #pragma unroll
    for (int i = 0; i < 16; i++) {
        float2 v = u2f2(a0[i]);
        float2 u = u2f2(a1[i]);
        int r = 2 * i;
        if (r < rows)     { o0[(size_t)r * 240] = v.x;       o0[(size_t)r * 240 + 120] = u.x; }
        if (r + 1 < rows) { o0[(size_t)(r + 1) * 240] = v.y; o0[(size_t)(r + 1) * 240 + 120] = u.y; }
    }
}

// ---------------- gx1 GEMM: [valid rows,80] x [80,240] + bias; rz-paired stores ----------------
__global__ void __launch_bounds__(128) gx1_kernel(const int* __restrict__ lens)
{
    int b = blockIdx.x;
    int t0 = blockIdx.y * 32;
    int len = lens[b];
    if (t0 >= len) return;
    int rows = len - t0; if (rows > 32) rows = 32;
    int tid = threadIdx.x;
    __shared__ __align__(16) float Xt[80][36];

    const float4* xb = (const float4*)(g_out0 + ((size_t)b * TT + t0) * 80);
    for (int idx = tid; idx < 32 * 20; idx += 128) {
        int r = idx / 20, c4 = idx % 20;
        float4 v = (r < rows) ? xb[r * 20 + c4] : make_float4(0.f, 0.f, 0.f, 0.f);
        Xt[4 * c4 + 0][r] = v.x;
        Xt[4 * c4 + 1][r] = v.y;
        Xt[4 * c4 + 2][r] = v.z;
        Xt[4 * c4 + 3][r] = v.w;
    }
    __syncthreads();
    if (tid >= 120) return;
    int j0 = tid, j1 = tid + 120;
    u64 a0[16], a1[16];
    {
        float b0 = g_bih1cat[j0], b1 = g_bih1cat[j1];
        u64 i0 = f2u2(b0, b0), i1 = f2u2(b1, b1);
        #pragma unroll
        for (int i = 0; i < 16; i++) { a0[i] = i0; a1[i] = i1; }
    }
    #pragma unroll 4
    for (int k = 0; k < 80; k++) {
        float w0 = g_Wih1T[k * 240 + j0];
        float w1 = g_Wih1T[k * 240 + j1];
        u64 ww0 = f2u2(w0, w0), ww1 = f2u2(w1, w1);
        const ulonglong2* ap = (const ulonglong2*)(&Xt[k][0]);
        #pragma unroll
        for (int p = 0; p < 8; p++) {
            ulonglong2 a = ap[p];
            a0[2 * p + 0] = fma2(a.x, ww0, a0[2 * p + 0]);
            a0[2 * p + 1] = fma2(a.y, ww0, a0[2 * p + 1]);
            a1[2 * p + 0] = fma2(a.x, ww1, a1[2 * p + 0]);
            a1[2 * p + 1] = fma2(a.y, ww1, a1[2 * p + 1]);
        }
    }
    int noff = rz_off(tid);
    float* o0 = g_gx1 + ((size_t)b * TT + t0) * 240 + noff;
    #pragma unroll
    for (int i = 0; i < 16; i++) {
        float2 v = u2f2(a0[i]);
        float2 u = u2f2(a1[i]);
        int r = 2 * i;
        if (r < rows)     { o0[(size_t)r * 240] = v.x;       o0[(size_t)r * 240 + 120] = u.x; }
        if (r + 1 < rows) { o0[(size_t)(r + 1) * 240] = v.y; o0[(size_t)(r + 1) * 240 + 120] = u.y; }
    }
}

// ---- shared recurrence step body: rz-paired gate loads (LDG.64 + scalar per unit) ----
#define GRU_CORE(PR, PZ, PN, QR, QZ, QN, EBASE, STRIDE_EXPR, ACT_EXTRA0, ACT_EXTRA1)        \
    {                                                                                       \
        float xr = PR, xz = PZ, xn = PN, yr = QR, yz = QZ, yn = QN;                         \
        {                                                                                   \
            const float* e_ = (EBASE) + (STRIDE_EXPR);                                      \
            float2 rz0_ = *(const float2*)(e_ + 2 * u0);                                    \
            float2 rz1_ = *(const float2*)(e_ + 2 * u1c);                                   \
            PR = rz0_.x; PZ = rz0_.y; PN = e_[80 + u0];                                     \
            QR = rz1_.x; QZ = rz1_.y; QN = e_[80 + u1c];                                    \
        }                                                                                   \
        u64 a0a = bbu[0], a0b = 0ull;                                                       \
        u64 a1a = bbu[1], a1b = 0ull;                                                       \
        u64 a2a = bbu[2], a2b = 0ull;                                                       \
        u64 a3a = bbu[3], a3b = 0ull;                                                       \
        const ulonglong2* hq = (const ulonglong2*)hsm;                                      \
        _Pragma("unroll")                                                                   \
        for (int q = 0; q < 5; q++) {                                                       \
            ulonglong2 hA = hq[2 * q], hB = hq[2 * q + 1];                                  \
            a0a = fma2(w[0][4*q],   hA.x, a0a); a0a = fma2(w[0][4*q+1], hA.y, a0a);         \
            a0b = fma2(w[0][4*q+2], hB.x, a0b); a0b = fma2(w[0][4*q+3], hB.y, a0b);         \
            a1a = fma2(w[1][4*q],   hA.x, a1a); a1a = fma2(w[1][4*q+1], hA.y, a1a);         \
            a1b = fma2(w[1][4*q+2], hB.x, a1b); a1b = fma2(w[1][4*q+3], hB.y, a1b);         \
            a2a = fma2(w[2][4*q],   hA.x, a2a); a2a = fma2(w[2][4*q+1], hA.y, a2a);         \
            a2b = fma2(w[2][4*q+2], hB.x, a2b); a2b = fma2(w[2][4*q+3], hB.y, a2b);         \
            a3a = fma2(w[3][4*q],   hA.x, a3a); a3a = fma2(w[3][4*q+1], hA.y, a3a);         \
            a3b = fma2(w[3][4*q+2], hB.x, a3b); a3b = fma2(w[3][4*q+3], hB.y, a3b);         \
        }                                                                                   \
        float2 p0 = u2f2(add2(a0a, a0b));                                                   \
        float2 p1 = u2f2(add2(a1a, a1b));                                                   \
        float2 p2 = u2f2(add2(a2a, a2b));                                                   \
        float2 p3 = u2f2(add2(a3a, a3b));                                                   \
        float d0 = p0.x + p0.y;                                                             \
        float d1 = p1.x + p1.y;                                                             \
        float d2 = p2.x + p2.y;                                                             \
        float d3 = p3.x + p3.y;                                                             \
        float s1 = __shfl_sync(FULL, d1, (lane + 8)  & 31);                                 \
        float s2 = __shfl_sync(FULL, d2, (lane + 8)  & 31);                                 \
        float s3 = __shfl_sync(FULL, d2, (lane + 16) & 31);                                 \
        float s4 = __shfl_sync(FULL, d3, (lane + 16) & 31);                                 \
        float zv0 = (lane < 24) ? s1 : s2;                                                  \
        float nv0 = (lane < 16) ? s3 : s4;                                                  \
        {                                                                                   \
            float r = sigA(xr + d0);                                                        \
            float z = sigA(xz + zv0);                                                       \
            float n = tanhA(fmaf(r, nv0, xn));                                              \
            h0 = fmaf(z, h0 - n, n);                                                        \
            hsm[u0] = h0;                                                                   \
            ACT_EXTRA0;                                                                     \
        }                                                                                   \
        {                                                                                   \
            float r = sigA(yr + d1);                                                        \
            float z = sigA(yz + s2);                                                        \
            float n = tanhA(fmaf(r, s4, yn));                                               \
            h1 = fmaf(z, h1 - n, n);                                                        \
            hsm[h1idx] = h1;                                                                \
            ACT_EXTRA1;                                                                     \
        }                                                                                   \
        __syncwarp();                                                                       \
    }

// ---------------- Layer 0 ----------------
__global__ void __launch_bounds__(128) gru_layer0(
    const int* __restrict__ text, const int* __restrict__ lens,
    const float* __restrict__ bhh0f, const float* __restrict__ bhh0b)
{
    int wid = threadIdx.x >> 5, lane = threadIdx.x & 31;
    int wgid = blockIdx.x * 4 + wid;
    __shared__ int toks_s[4][TT];
    __shared__ __align__(16) float h_s[4][80];
    if (wgid >= 512) return;
    int* toks = toks_s[wid];
    float* hsm = h_s[wid];
    const unsigned FULL = 0xffffffffu;
    float* sinkp = g_sink + (size_t)wgid * 32 + lane;

    for (int slot = 0; slot < 2; slot++) {
        int c = slot ? (1023 - wgid) : wgid;
        int b = g_perm[c >> 1];
        int dir = c & 1;
        int len = lens[b];

        for (int i = lane; i < len; i += 32) toks[i] = text[b * TT + i];

        u64 w[4][20];
        u64 bbu[4];
        const u64* wp = (const u64*)g_Whh0P4 + (size_t)dir * 120 * 20;
        const float* bhh = dir ? bhh0b : bhh0f;
        #pragma unroll
        for (int m = 0; m < 4; m++) {
            int f = lane + 32 * m;
            if (f < 120) {
                const u64* wf = wp + f * 20;
                #pragma unroll
                for (int k2 = 0; k2 < 20; k2++) w[m][k2] = wf[k2];
                bbu[m] = f2u2(bhh[f], 0.f);
            } else {
                #pragma unroll
                for (int k2 = 0; k2 < 20; k2++) w[m][k2] = 0ull;
                bbu[m] = 0ull;
            }
        }
        hsm[lane] = 0.f;
        if (lane < 16) hsm[32 + lane] = 0.f;
        __syncwarp();

        int t0 = dir ? (len - 1) : 0;
        int td = dir ? -1 : 1;
        const float* embW = g_embW0 + dir * 120;
        int u0 = lane;
        int u1c = 32 + (lane & 7);
        bool two = (lane < 8);
        int h1idx = two ? u1c : (40 + lane);

        float Ar, Az, An, Cr, Cz, Cn, Br, Bz, Bn, Dr, Dz, Dn;
        {
            const float* e0 = embW + (size_t)toks[t0] * 240;
            float2 rz0 = *(const float2*)(e0 + 2 * u0);
            float2 rz1 = *(const float2*)(e0 + 2 * u1c);
            Ar = rz0.x; Az = rz0.y; An = e0[80 + u0];
            Cr = rz1.x; Cz = rz1.y; Cn = e0[80 + u1c];
            int s1i = (len > 1) ? 1 : 0;
            const float* e1 = embW + (size_t)toks[t0 + s1i * td] * 240;
            float2 rz2 = *(const float2*)(e1 + 2 * u0);
            float2 rz3 = *(const float2*)(e1 + 2 * u1c);
            Br = rz2.x; Bz = rz2.y; Bn = e1[80 + u0];
            Dr = rz3.x; Dz = rz3.y; Dn = e1[80 + u1c];
        }
        float h0 = 0.f, h1 = 0.f;
        float* outb = g_out0 + ((size_t)b * TT + t0) * 80 + dir * 40;
        long ostep = (long)td * 80;

        for (int s = 0; s < len; s += 2) {
            {
                int sp = (s + 2 < len) ? s + 2 : len - 1;
                GRU_CORE(Ar, Az, An, Cr, Cz, Cn, embW,
                         (size_t)toks[t0 + sp * td] * 240,
                         outb[u0] = h0,
                         *(two ? (outb + u1c) : sinkp) = h1)
                outb += ostep;
            }
            if (s + 1 >= len) break;
            {
                int sp = (s + 3 < len) ? s + 3 : len - 1;
                GRU_CORE(Br, Bz, Bn, Dr, Dz, Dn, embW,
                         (size_t)toks[t0 + sp * td] * 240,
                         outb[u0] = h0,
                         *(two ? (outb + u1c) : sinkp) = h1)
                outb += ostep;
            }
        }
        float* hl = dir ? g_hb0 : g_hf0;
        hl[b * HH + u0] = h0;
        if (two) hl[b * HH + u1c] = h1;
    }
}

// ---------------- Layer 1 ----------------
__global__ void __launch_bounds__(128) gru_layer1(
    const int* __restrict__ lens,
    const float* __restrict__ bhh1f, const float* __restrict__ bhh1b)
{
    int wid = threadIdx.x >> 5, lane = threadIdx.x & 31;
    int wgid = blockIdx.x * 4 + wid;
    __shared__ __align__(16) float h_s[4][80];
    if (wgid >= 512) return;
    float* hsm = h_s[wid];
    const unsigned FULL = 0xffffffffu;

    for (int slot = 0; slot < 2; slot++) {
        int c = slot ? (1023 - wgid) : wgid;
        int b = g_perm[c >> 1];
        int dir = c & 1;
        int len = lens[b];

        u64 w[4][20];
        u64 bbu[4];
        const u64* wp = (const u64*)g_Whh1P4 + (size_t)dir * 120 * 20;
        const float* bhh = dir ? bhh1b : bhh1f;
        #pragma unroll
        for (int m = 0; m < 4; m++) {
            int f = lane + 32 * m;
            if (f < 120) {
                const u64* wf = wp + f * 20;
                #pragma unroll
                for (int k2 = 0; k2 < 20; k2++) w[m][k2] = wf[k2];
                bbu[m] = f2u2(bhh[f], 0.f);
            } else {
                #pragma unroll
                for (int k2 = 0; k2 < 20; k2++) w[m][k2] = 0ull;
                bbu[m] = 0ull;
            }
        }
        hsm[lane] = 0.f;
        if (lane < 16) hsm[32 + lane] = 0.f;
        __syncwarp();

        int t0 = dir ? (len - 1) : 0;
        int td = dir ? -1 : 1;
        const float* gxb = g_gx1 + ((size_t)b * TT) * 240 + dir * 120;
        int u0 = lane;
        int u1c = 32 + (lane & 7);
        bool two = (lane < 8);
        int h1idx = two ? u1c : (40 + lane);

        float Ar, Az, An, Cr, Cz, Cn, Br, Bz, Bn, Dr, Dz, Dn;
        {
            const float* e0 = gxb + (size_t)t0 * 240;
            float2 rz0 = *(const float2*)(e0 + 2 * u0);
            float2 rz1 = *(const float2*)(e0 + 2 * u1c);
            Ar = rz0.x; Az = rz0.y; An = e0[80 + u0];
            Cr = rz1.x; Cz = rz1.y; Cn = e0[80 + u1c];
            int s1i = (len > 1) ? 1 : 0;
            const float* e1 = gxb + (size_t)(t0 + s1i * td) * 240;
            float2 rz2 = *(const float2*)(e1 + 2 * u0);
            float2 rz3 = *(const float2*)(e1 + 2 * u1c);
            Br = rz2.x; Bz = rz2.y; Bn = e1[80 + u0];
            Dr = rz3.x; Dz = rz3.y; Dn = e1[80 + u1c];
        }
        float h0 = 0.f, h1 = 0.f;
        float sum0 = 0.f, max0 = -1e30f, sum1 = 0.f, max1 = -1e30f;

        for (int s = 0; s < len; s += 2) {
            {
                int sp = (s + 2 < len) ? s + 2 : len - 1;
                GRU_CORE(Ar, Az, An, Cr, Cz, Cn, gxb,
                         (size_t)(t0 + sp * td) * 240,
                         { sum0 += h0; max0 = fmaxf(max0, h0); },
                         { sum1 += h1; max1 = fmaxf(max1, h1); })
            }
            if (s + 1 >= len) break;
            {
                int sp = (s + 3 < len) ? s + 3 : len - 1;
                GRU_CORE(Br, Bz, Bn, Dr, Dz, Dn, gxb,
                         (size_t)(t0 + sp * td) * 240,
                         { sum0 += h0; max0 = fmaxf(max0, h0); },
                         { sum1 += h1; max1 = fmaxf(max1, h1); })
            }
        }
        float inv = __fdividef(1.f, (float)len);
        g_avgp[b * 80 + dir * 40 + u0] = sum0 * inv;
        g_maxp[b * 80 + dir * 40 + u0] = max0;
        float* hl = dir ? g_hb1 : g_hf1;
        hl[b * HH + u0] = h0;
        if (two) {
            g_avgp[b * 80 + dir * 40 + u1c] = sum1 * inv;
            g_maxp[b * 80 + dir * 40 + u1c] = max1;
            hl[b * HH + u1c] = h1;
        }
    }
}

// ---------------- Head ----------------
__global__ void __launch_bounds__(128) fc_kernel(
    const float* __restrict__ fc1_b, const float* __restrict__ fc2_W,
    const float* __restrict__ fc2_b, float* __restrict__ out)
{
    int b = blockIdx.x, j = threadIdx.x;
    __shared__ float cat[320];
    for (int i = j; i < 320; i += 128) {
        float v;
        if (i < 40)       v = g_hb1[b * 40 + i];
        else if (i < 80)  v = g_hf1[b * 40 + (i - 40)];
        else if (i < 120) v = g_hb0[b * 40 + (i - 80)];
        else if (i < 160) v = g_hf0[b * 40 + (i - 120)];
        else if (i < 240) v = g_avgp[b * 80 + (i - 160)];
        else              v = g_maxp[b * 80 + (i - 240)];
        cat[i] = v;
    }
    __syncthreads();
    float acc = fc1_b[j];
    #pragma unroll 8
    for (int k = 0; k < 320; k++)
        acc = fmaf(g_fc1WT[k * 128 + j], cat[k], acc);
    float h = (acc >= 0.f) ? acc : 0.01f * acc;
    float p = h * fc2_W[j];
    #pragma unroll
    for (int o = 16; o > 0; o >>= 1) p += __shfl_down_sync(0xffffffffu, p, o);
    __shared__ float red[4];
    if ((j & 31) == 0) red[j >> 5] = p;
    __syncthreads();
    if (j == 0) out[b] = (red[0] + red[1] + red[2] + red[3]) + fc2_b[0];
}

// ---------------- Launch ----------------
extern "C" void kernel_launch(void* const* d_in, const int* in_sizes, int n_in,
                              void* d_out, int out_size)
{
    const int*   text     = (const int*)d_in[0];
    const int*   text_len = (const int*)d_in[1];
    const float* emb      = (const float*)d_in[2];
    const float* Wih0f = (const float*)d_in[3];
    const float* Whh0f = (const float*)d_in[4];
    const float* bih0f = (const float*)d_in[5];
    const float* bhh0f = (const float*)d_in[6];
    const float* Wih0b = (const float*)d_in[7];
    const float* Whh0b = (const float*)d_in[8];
    const float* bih0b = (const float*)d_in[9];
    const float* bhh0b = (const float*)d_in[10];
    const float* Wih1f = (const float*)d_in[11];
    const float* Whh1f = (const float*)d_in[12];
    const float* bih1f = (const float*)d_in[13];
    const float* bhh1f = (const float*)d_in[14];
    const float* Wih1b = (const float*)d_in[15];
    const float* Whh1b = (const float*)d_in[16];
    const float* bih1b = (const float*)d_in[17];
    const float* bhh1b = (const float*)d_in[18];
    const float* fc1_W = (const float*)d_in[19];
    const float* fc1_b = (const float*)d_in[20];
    const float* fc2_W = (const float*)d_in[21];
    const float* fc2_b = (const float*)d_in[22];
    float* out = (float*)d_out;

    prep_weights<<<160, 256>>>(Wih0f, Whh0f, bih0f, Wih0b, Whh0b, bih0b,
                               Wih1f, Whh1f, bih1f, Wih1b, Whh1b, bih1b, fc1_W);
    sort_kernel<<<1, BB>>>(text_len);
    embw_kernel<<<(VV + 31) / 32, 128>>>(emb);
    gru_layer0<<<148, 128>>>(text, text_len, bhh0f, bhh0b);
    gx1_kernel<<<dim3(BB, TT / 32), 128>>>(text_len);
    gru_layer1<<<148, 128>>>(text_len, bhh1f, bhh1b);
    fc_kernel<<<BB, 128>>>(fc1_b, fc2_W, fc2_b, out);
}

// round 17
// speedup vs baseline: 1.8791x; 1.0383x over previous
#include <cuda_runtime.h>
#include <cuda_bf16.h>
#include <math.h>

// ---------------- Problem dims ----------------
#define BB 512
#define TT 512
#define VV 50000
#define EE 100
#define HH 40

typedef unsigned long long u64;

// ---------------- f32x2 packed helpers ----------------
__device__ __forceinline__ u64 f2u2(float x, float y) {
    u64 u; asm("mov.b64 %0, {%1,%2};" : "=l"(u) : "f"(x), "f"(y)); return u;
}
__device__ __forceinline__ u64 fma2(u64 a, u64 b, u64 c) {
    u64 d; asm("fma.rn.f32x2 %0, %1, %2, %3;" : "=l"(d) : "l"(a), "l"(b), "l"(c)); return d;
}
__device__ __forceinline__ u64 add2(u64 a, u64 b) {
    u64 d; asm("add.rn.f32x2 %0, %1, %2;" : "=l"(d) : "l"(a), "l"(b)); return d;
}
__device__ __forceinline__ float2 u2f2(u64 u) {
    float lo, hi; asm("mov.b64 {%0,%1}, %2;" : "=f"(lo), "=f"(hi) : "l"(u));
    return make_float2(lo, hi);
}

// single-MUFU tanh (sm_75+)
__device__ __forceinline__ float tanhA(float x) {
    float y; asm("tanh.approx.f32 %0, %1;" : "=f"(y) : "f"(x)); return y;
}
__device__ __forceinline__ float sigA(float x) {
    return fmaf(tanhA(0.5f * x), 0.5f, 0.5f);
}

// ---------------- Device scratch ----------------
__device__ __align__(16) float g_embW0[VV * 240];            // [v][dir0: r|z|n][dir1: r|z|n]
__device__ __align__(16) float g_out0[BB * TT * 80];
__device__ __align__(16) float g_gx1[(size_t)BB * TT * 240];
__device__ __align__(16) float g_Wih0T[EE * 240];
__device__ __align__(16) float g_bih0cat[240];
__device__ __align__(16) float g_Wih1T[80 * 240];
__device__ __align__(16) float g_bih1cat[240];
// 4-output gate-owner pack: [dir][f(0..119)][k2(0..19)] u64 pairs
__device__ __align__(16) float g_Whh0P4[2 * 120 * 20 * 2];
__device__ __align__(16) float g_Whh1P4[2 * 120 * 20 * 2];
__device__ __align__(16) float g_fc1WT[320 * 128];
__device__ float g_hf0[BB * HH], g_hb0[BB * HH], g_hf1[BB * HH], g_hb1[BB * HH];
__device__ float g_avgp[BB * 80], g_maxp[BB * 80];
__device__ int g_perm[BB];
__device__ float g_sink[592 * 32];

// ---------------- Prep ----------------
__global__ void prep_weights(
    const float* __restrict__ Wih0f, const float* __restrict__ Whh0f,
    const float* __restrict__ bih0f,
    const float* __restrict__ Wih0b, const float* __restrict__ Whh0b,
    const float* __restrict__ bih0b,
    const float* __restrict__ Wih1f, const float* __restrict__ Whh1f,
    const float* __restrict__ bih1f,
    const float* __restrict__ Wih1b, const float* __restrict__ Whh1b,
    const float* __restrict__ bih1b,
    const float* __restrict__ fc1_W)
{
    int g = blockIdx.x * blockDim.x + threadIdx.x;
    int NT = gridDim.x * blockDim.x;
    for (int i = g; i < EE * 240; i += NT) {
        int k = i / 240, j = i % 240;
        g_Wih0T[i] = (j < 120) ? Wih0f[j * EE + k] : Wih0b[(j - 120) * EE + k];
    }
    for (int i = g; i < 80 * 240; i += NT) {
        int k = i / 240, j = i % 240;
        g_Wih1T[i] = (j < 120) ? Wih1f[j * 80 + k] : Wih1b[(j - 120) * 80 + k];
    }
    for (int i = g; i < 240; i += NT) {
        g_bih0cat[i] = (i < 120) ? bih0f[i] : bih0b[i - 120];
        g_bih1cat[i] = (i < 120) ? bih1f[i] : bih1b[i - 120];
    }
    for (int i = g; i < 2 * 120 * 20 * 2; i += NT) {
        int c = i & 1;
        int t = i >> 1;
        int k2 = t % 20;
        int f = (t / 20) % 120;
        int dir = t / 2400;
        int src = f * 40 + 2 * k2 + c;
        g_Whh0P4[i] = (dir ? Whh0b : Whh0f)[src];
        g_Whh1P4[i] = (dir ? Whh1b : Whh1f)[src];
    }
    for (int i = g; i < 320 * 128; i += NT) {
        int k = i / 128, q = i % 128;
        g_fc1WT[i] = fc1_W[q * 320 + k];
    }
}

// ---------------- Length sort (descending) ----------------
__global__ void sort_kernel(const int* __restrict__ lens)
{
    __shared__ int L[BB];
    int b = threadIdx.x;
    int lb = lens[b];
    L[b] = lb;
    __syncthreads();
    int r = 0;
    #pragma unroll 8
    for (int i = 0; i < BB; i++) {
        int li = L[i];
        r += (li > lb) || (li == lb && i < b);
    }
    g_perm[r] = b;
}

// ---------------- embW GEMM: paired adjacent columns (LDG.64 weights, float2 stores) ----------------
__global__ void __launch_bounds__(128) embw_kernel(const float* __restrict__ emb)
{
    int tid = threadIdx.x;
    int v0 = blockIdx.x * 32;
    int rows = VV - v0; if (rows > 32) rows = 32;
    __shared__ __align__(16) float Xt[100][36];

    const float4* xb = (const float4*)(emb + (size_t)v0 * EE);
    for (int idx = tid; idx < 32 * 25; idx += 128) {
        int r = idx / 25, c4 = idx % 25;
        float4 v = (r < rows) ? xb[r * 25 + c4] : make_float4(0.f, 0.f, 0.f, 0.f);
        Xt[4 * c4 + 0][r] = v.x;
        Xt[4 * c4 + 1][r] = v.y;
        Xt[4 * c4 + 2][r] = v.z;
        Xt[4 * c4 + 3][r] = v.w;
    }
    __syncthreads();
    if (tid >= 120) return;
    u64 a0[16], a1[16];
    {
        float2 bb = ((const float2*)g_bih0cat)[tid];
        u64 i0 = f2u2(bb.x, bb.x), i1 = f2u2(bb.y, bb.y);
        #pragma unroll
        for (int i = 0; i < 16; i++) { a0[i] = i0; a1[i] = i1; }
    }
    #pragma unroll 4
    for (int k = 0; k < 100; k++) {
        float2 wv = ((const float2*)(g_Wih0T + k * 240))[tid];
        u64 ww0 = f2u2(wv.x, wv.x), ww1 = f2u2(wv.y, wv.y);
        const ulonglong2* ap = (const ulonglong2*)(&Xt[k][0]);
        #pragma unroll
        for (int p = 0; p < 8; p++) {
            ulonglong2 a = ap[p];
            a0[2 * p + 0] = fma2(a.x, ww0, a0[2 * p + 0]);
            a0[2 * p + 1] = fma2(a.y, ww0, a0[2 * p + 1]);
            a1[2 * p + 0] = fma2(a.x, ww1, a1[2 * p + 0]);
            a1[2 * p + 1] = fma2(a.y, ww1, a1[2 * p + 1]);
        }
    }
    float* o0 = g_embW0 + (size_t)v0 * 240 + 2 * tid;
    #pragma unroll
    for (int i = 0; i < 16; i++) {
        float2 v = u2f2(a0[i]);
        float2 u = u2f2(a1[i]);
        int r = 2 * i;
        if (r < rows)     *(float2*)(o0 + (size_t)r * 240)       = make_float2(v.x, u.x);
        if (r + 1 < rows) *(float2*)(o0 + (size_t)(r + 1) * 240) = make_float2(v.y, u.y);
    }
}

// ---------------- gx1 GEMM: paired adjacent columns ----------------
__global__ void __launch_bounds__(128) gx1_kernel(const int* __restrict__ lens)
{
    int b = blockIdx.x;
    int t0 = blockIdx.y * 32;
    int len = lens[b];
    if (t0 >= len) return;
    int rows = len - t0; if (rows > 32) rows = 32;
    int tid = threadIdx.x;
    __shared__ __align__(16) float Xt[80][36];

    const float4* xb = (const float4*)(g_out0 + ((size_t)b * TT + t0) * 80);
    for (int idx = tid; idx < 32 * 20; idx += 128) {
        int r = idx / 20, c4 = idx % 20;
        float4 v = (r < rows) ? xb[r * 20 + c4] : make_float4(0.f, 0.f, 0.f, 0.f);
        Xt[4 * c4 + 0][r] = v.x;
        Xt[4 * c4 + 1][r] = v.y;
        Xt[4 * c4 + 2][r] = v.z;
        Xt[4 * c4 + 3][r] = v.w;
    }
    __syncthreads();
    if (tid >= 120) return;
    u64 a0[16], a1[16];
    {
        float2 bb = ((const float2*)g_bih1cat)[tid];
        u64 i0 = f2u2(bb.x, bb.x), i1 = f2u2(bb.y, bb.y);
        #pragma unroll
        for (int i = 0; i < 16; i++) { a0[i] = i0; a1[i] = i1; }
    }
    #pragma unroll 4
    for (int k = 0; k < 80; k++) {
        float2 wv = ((const float2*)(g_Wih1T + k * 240))[tid];
        u64 ww0 = f2u2(wv.x, wv.x), ww1 = f2u2(wv.y, wv.y);
        const ulonglong2* ap = (const ulonglong2*)(&Xt[k][0]);
        #pragma unroll
        for (int p = 0; p < 8; p++) {
            ulonglong2 a = ap[p];
            a0[2 * p + 0] = fma2(a.x, ww0, a0[2 * p + 0]);
            a0[2 * p + 1] = fma2(a.y, ww0, a0[2 * p + 1]);
            a1[2 * p + 0] = fma2(a.x, ww1, a1[2 * p + 0]);
            a1[2 * p + 1] = fma2(a.y, ww1, a1[2 * p + 1]);
        }
    }
    float* o0 = g_gx1 + ((size_t)b * TT + t0) * 240 + 2 * tid;
    #pragma unroll
    for (int i = 0; i < 16; i++) {
        float2 v = u2f2(a0[i]);
        float2 u = u2f2(a1[i]);
        int r = 2 * i;
        if (r < rows)     *(float2*)(o0 + (size_t)r * 240)       = make_float2(v.x, u.x);
        if (r + 1 < rows) *(float2*)(o0 + (size_t)(r + 1) * 240) = make_float2(v.y, u.y);
    }
}

// ---- shared recurrence step body (R13 champion, unchanged) ----
#define GRU_CORE(PR, PZ, PN, QR, QZ, QN, EBASE, STRIDE_EXPR, ACT_EXTRA0, ACT_EXTRA1)        \
    {                                                                                       \
        float xr = PR, xz = PZ, xn = PN, yr = QR, yz = QZ, yn = QN;                         \
        {                                                                                   \
            const float* e_ = (EBASE) + (STRIDE_EXPR);                                      \
            PR = e_[u0]; PZ = e_[40 + u0]; PN = e_[80 + u0];                                \
            QR = e_[u1c]; QZ = e_[40 + u1c]; QN = e_[80 + u1c];                             \
        }                                                                                   \
        u64 a0a = bbu[0], a0b = 0ull;                                                       \
        u64 a1a = bbu[1], a1b = 0ull;                                                       \
        u64 a2a = bbu[2], a2b = 0ull;                                                       \
        u64 a3a = bbu[3], a3b = 0ull;                                                       \
        const ulonglong2* hq = (const ulonglong2*)hsm;                                      \
        _Pragma("unroll")                                                                   \
        for (int q = 0; q < 5; q++) {                                                       \
            ulonglong2 hA = hq[2 * q], hB = hq[2 * q + 1];                                  \
            a0a = fma2(w[0][4*q],   hA.x, a0a); a0a = fma2(w[0][4*q+1], hA.y, a0a);         \
            a0b = fma2(w[0][4*q+2], hB.x, a0b); a0b = fma2(w[0][4*q+3], hB.y, a0b);         \
            a1a = fma2(w[1][4*q],   hA.x, a1a); a1a = fma2(w[1][4*q+1], hA.y, a1a);         \
            a1b = fma2(w[1][4*q+2], hB.x, a1b); a1b = fma2(w[1][4*q+3], hB.y, a1b);         \
            a2a = fma2(w[2][4*q],   hA.x, a2a); a2a = fma2(w[2][4*q+1], hA.y, a2a);         \
            a2b = fma2(w[2][4*q+2], hB.x, a2b); a2b = fma2(w[2][4*q+3], hB.y, a2b);         \
            a3a = fma2(w[3][4*q],   hA.x, a3a); a3a = fma2(w[3][4*q+1], hA.y, a3a);         \
            a3b = fma2(w[3][4*q+2], hB.x, a3b); a3b = fma2(w[3][4*q+3], hB.y, a3b);         \
        }                                                                                   \
        float2 p0 = u2f2(add2(a0a, a0b));                                                   \
        float2 p1 = u2f2(add2(a1a, a1b));                                                   \
        float2 p2 = u2f2(add2(a2a, a2b));                                                   \
        float2 p3 = u2f2(add2(a3a, a3b));                                                   \
        float d0 = p0.x + p0.y;                                                             \
        float d1 = p1.x + p1.y;                                                             \
        float d2 = p2.x + p2.y;                                                             \
        float d3 = p3.x + p3.y;                                                             \
        float s1 = __shfl_sync(FULL, d1, (lane + 8)  & 31);                                 \
        float s2 = __shfl_sync(FULL, d2, (lane + 8)  & 31);                                 \
        float s3 = __shfl_sync(FULL, d2, (lane + 16) & 31);                                 \
        float s4 = __shfl_sync(FULL, d3, (lane + 16) & 31);                                 \
        float zv0 = (lane < 24) ? s1 : s2;                                                  \
        float nv0 = (lane < 16) ? s3 : s4;                                                  \
        {                                                                                   \
            float r = sigA(xr + d0);                                                        \
            float z = sigA(xz + zv0);                                                       \
            float n = tanhA(fmaf(r, nv0, xn));                                              \
            h0 = fmaf(z, h0 - n, n);                                                        \
            hsm[u0] = h0;                                                                   \
            ACT_EXTRA0;                                                                     \
        }                                                                                   \
        {                                                                                   \
            float r = sigA(yr + d1);                                                        \
            float z = sigA(yz + s2);                                                        \
            float n = tanhA(fmaf(r, s4, yn));                                               \
            h1 = fmaf(z, h1 - n, n);                                                        \
            hsm[h1idx] = h1;                                                                \
            ACT_EXTRA1;                                                                     \
        }                                                                                   \
        __syncwarp();                                                                       \
    }

// ---------------- Layer 0 (R13 champion, unchanged) ----------------
__global__ void __launch_bounds__(128) gru_layer0(
    const int* __restrict__ text, const int* __restrict__ lens,
    const float* __restrict__ bhh0f, const float* __restrict__ bhh0b)
{
    int wid = threadIdx.x >> 5, lane = threadIdx.x & 31;
    int wgid = blockIdx.x * 4 + wid;
    __shared__ int toks_s[4][TT];
    __shared__ __align__(16) float h_s[4][80];
    if (wgid >= 512) return;
    int* toks = toks_s[wid];
    float* hsm = h_s[wid];
    const unsigned FULL = 0xffffffffu;
    float* sinkp = g_sink + (size_t)wgid * 32 + lane;

    for (int slot = 0; slot < 2; slot++) {
        int c = slot ? (1023 - wgid) : wgid;
        int b = g_perm[c >> 1];
        int dir = c & 1;
        int len = lens[b];

        for (int i = lane; i < len; i += 32) toks[i] = text[b * TT + i];

        u64 w[4][20];
        u64 bbu[4];
        const u64* wp = (const u64*)g_Whh0P4 + (size_t)dir * 120 * 20;
        const float* bhh = dir ? bhh0b : bhh0f;
        #pragma unroll
        for (int m = 0; m < 4; m++) {
            int f = lane + 32 * m;
            if (f < 120) {
                const u64* wf = wp + f * 20;
                #pragma unroll
                for (int k2 = 0; k2 < 20; k2++) w[m][k2] = wf[k2];
                bbu[m] = f2u2(bhh[f], 0.f);
            } else {
                #pragma unroll
                for (int k2 = 0; k2 < 20; k2++) w[m][k2] = 0ull;
                bbu[m] = 0ull;
            }
        }
        hsm[lane] = 0.f;
        if (lane < 16) hsm[32 + lane] = 0.f;
        __syncwarp();

        int t0 = dir ? (len - 1) : 0;
        int td = dir ? -1 : 1;
        const float* embW = g_embW0 + dir * 120;
        int u0 = lane;
        int u1c = 32 + (lane & 7);
        bool two = (lane < 8);
        int h1idx = two ? u1c : (40 + lane);

        float Ar, Az, An, Cr, Cz, Cn, Br, Bz, Bn, Dr, Dz, Dn;
        {
            const float* e0 = embW + (size_t)toks[t0] * 240;
            Ar = e0[u0]; Az = e0[40 + u0]; An = e0[80 + u0];
            Cr = e0[u1c]; Cz = e0[40 + u1c]; Cn = e0[80 + u1c];
            int s1i = (len > 1) ? 1 : 0;
            const float* e1 = embW + (size_t)toks[t0 + s1i * td] * 240;
            Br = e1[u0]; Bz = e1[40 + u0]; Bn = e1[80 + u0];
            Dr = e1[u1c]; Dz = e1[40 + u1c]; Dn = e1[80 + u1c];
        }
        float h0 = 0.f, h1 = 0.f;
        float* outb = g_out0 + ((size_t)b * TT + t0) * 80 + dir * 40;
        long ostep = (long)td * 80;

        for (int s = 0; s < len; s += 2) {
            {
                int sp = (s + 2 < len) ? s + 2 : len - 1;
                GRU_CORE(Ar, Az, An, Cr, Cz, Cn, embW,
                         (size_t)toks[t0 + sp * td] * 240,
                         outb[u0] = h0,
                         *(two ? (outb + u1c) : sinkp) = h1)
                outb += ostep;
            }
            if (s + 1 >= len) break;
            {
                int sp = (s + 3 < len) ? s + 3 : len - 1;
                GRU_CORE(Br, Bz, Bn, Dr, Dz, Dn, embW,
                         (size_t)toks[t0 + sp * td] * 240,
                         outb[u0] = h0,
                         *(two ? (outb + u1c) : sinkp) = h1)
                outb += ostep;
            }
        }
        float* hl = dir ? g_hb0 : g_hf0;
        hl[b * HH + u0] = h0;
        if (two) hl[b * HH + u1c] = h1;
    }
}

// ---------------- Layer 1 (R13 champion, unchanged) ----------------
__global__ void __launch_bounds__(128) gru_layer1(
    const int* __restrict__ lens,
    const float* __restrict__ bhh1f, const float* __restrict__ bhh1b)
{
    int wid = threadIdx.x >> 5, lane = threadIdx.x & 31;
    int wgid = blockIdx.x * 4 + wid;
    __shared__ __align__(16) float h_s[4][80];
    if (wgid >= 512) return;
    float* hsm = h_s[wid];
    const unsigned FULL = 0xffffffffu;

    for (int slot = 0; slot < 2; slot++) {
        int c = slot ? (1023 - wgid) : wgid;
        int b = g_perm[c >> 1];
        int dir = c & 1;
        int len = lens[b];

        u64 w[4][20];
        u64 bbu[4];
        const u64* wp = (const u64*)g_Whh1P4 + (size_t)dir * 120 * 20;
        const float* bhh = dir ? bhh1b : bhh1f;
        #pragma unroll
        for (int m = 0; m < 4; m++) {
            int f = lane + 32 * m;
            if (f < 120) {
                const u64* wf = wp + f * 20;
                #pragma unroll
                for (int k2 = 0; k2 < 20; k2++) w[m][k2] = wf[k2];
                bbu[m] = f2u2(bhh[f], 0.f);
            } else {
                #pragma unroll
                for (int k2 = 0; k2 < 20; k2++) w[m][k2] = 0ull;
                bbu[m] = 0ull;
            }
        }
        hsm[lane] = 0.f;
        if (lane < 16) hsm[32 + lane] = 0.f;
        __syncwarp();

        int t0 = dir ? (len - 1) : 0;
        int td = dir ? -1 : 1;
        const float* gxb = g_gx1 + ((size_t)b * TT) * 240 + dir * 120;
        int u0 = lane;
        int u1c = 32 + (lane & 7);
        bool two = (lane < 8);
        int h1idx = two ? u1c : (40 + lane);

        float Ar, Az, An, Cr, Cz, Cn, Br, Bz, Bn, Dr, Dz, Dn;
        {
            const float* e0 = gxb + (size_t)t0 * 240;
            Ar = e0[u0]; Az = e0[40 + u0]; An = e0[80 + u0];
            Cr = e0[u1c]; Cz = e0[40 + u1c]; Cn = e0[80 + u1c];
            int s1i = (len > 1) ? 1 : 0;
            const float* e1 = gxb + (size_t)(t0 + s1i * td) * 240;
            Br = e1[u0]; Bz = e1[40 + u0]; Bn = e1[80 + u0];
            Dr = e1[u1c]; Dz = e1[40 + u1c]; Dn = e1[80 + u1c];
        }
        float h0 = 0.f, h1 = 0.f;
        float sum0 = 0.f, max0 = -1e30f, sum1 = 0.f, max1 = -1e30f;

        for (int s = 0; s < len; s += 2) {
            {
                int sp = (s + 2 < len) ? s + 2 : len - 1;
                GRU_CORE(Ar, Az, An, Cr, Cz, Cn, gxb,
                         (size_t)(t0 + sp * td) * 240,
                         { sum0 += h0; max0 = fmaxf(max0, h0); },
                         { sum1 += h1; max1 = fmaxf(max1, h1); })
            }
            if (s + 1 >= len) break;
            {
                int sp = (s + 3 < len) ? s + 3 : len - 1;
                GRU_CORE(Br, Bz, Bn, Dr, Dz, Dn, gxb,
                         (size_t)(t0 + sp * td) * 240,
                         { sum0 += h0; max0 = fmaxf(max0, h0); },
                         { sum1 += h1; max1 = fmaxf(max1, h1); })
            }
        }
        float inv = __fdividef(1.f, (float)len);
        g_avgp[b * 80 + dir * 40 + u0] = sum0 * inv;
        g_maxp[b * 80 + dir * 40 + u0] = max0;
        float* hl = dir ? g_hb1 : g_hf1;
        hl[b * HH + u0] = h0;
        if (two) {
            g_avgp[b * 80 + dir * 40 + u1c] = sum1 * inv;
            g_maxp[b * 80 + dir * 40 + u1c] = max1;
            hl[b * HH + u1c] = h1;
        }
    }
}

// ---------------- Head ----------------
__global__ void __launch_bounds__(128) fc_kernel(
    const float* __restrict__ fc1_b, const float* __restrict__ fc2_W,
    const float* __restrict__ fc2_b, float* __restrict__ out)
{
    int b = blockIdx.x, j = threadIdx.x;
    __shared__ float cat[320];
    for (int i = j; i < 320; i += 128) {
        float v;
        if (i < 40)       v = g_hb1[b * 40 + i];
        else if (i < 80)  v = g_hf1[b * 40 + (i - 40)];
        else if (i < 120) v = g_hb0[b * 40 + (i - 80)];
        else if (i < 160) v = g_hf0[b * 40 + (i - 120)];
        else if (i < 240) v = g_avgp[b * 80 + (i - 160)];
        else              v = g_maxp[b * 80 + (i - 240)];
        cat[i] = v;
    }
    __syncthreads();
    float acc = fc1_b[j];
    #pragma unroll 8
    for (int k = 0; k < 320; k++)
        acc = fmaf(g_fc1WT[k * 128 + j], cat[k], acc);
    float h = (acc >= 0.f) ? acc : 0.01f * acc;
    float p = h * fc2_W[j];
    #pragma unroll
    for (int o = 16; o > 0; o >>= 1) p += __shfl_down_sync(0xffffffffu, p, o);
    __shared__ float red[4];
    if ((j & 31) == 0) red[j >> 5] = p;
    __syncthreads();
    if (j == 0) out[b] = (red[0] + red[1] + red[2] + red[3]) + fc2_b[0];
}

// ---------------- Launch ----------------
extern "C" void kernel_launch(void* const* d_in, const int* in_sizes, int n_in,
                              void* d_out, int out_size)
{
    const int*   text     = (const int*)d_in[0];
    const int*   text_len = (const int*)d_in[1];
    const float* emb      = (const float*)d_in[2];
    const float* Wih0f = (const float*)d_in[3];
    const float* Whh0f = (const float*)d_in[4];
    const float* bih0f = (const float*)d_in[5];
    const float* bhh0f = (const float*)d_in[6];
    const float* Wih0b = (const float*)d_in[7];
    const float* Whh0b = (const float*)d_in[8];
    const float* bih0b = (const float*)d_in[9];
    const float* bhh0b = (const float*)d_in[10];
    const float* Wih1f = (const float*)d_in[11];
    const float* Whh1f = (const float*)d_in[12];
    const float* bih1f = (const float*)d_in[13];
    const float* bhh1f = (const float*)d_in[14];
    const float* Wih1b = (const float*)d_in[15];
    const float* Whh1b = (const float*)d_in[16];
    const float* bih1b = (const float*)d_in[17];
    const float* bhh1b = (const float*)d_in[18];
    const float* fc1_W = (const float*)d_in[19];
    const float* fc1_b = (const float*)d_in[20];
    const float* fc2_W = (const float*)d_in[21];
    const float* fc2_b = (const float*)d_in[22];
    float* out = (float*)d_out;

    prep_weights<<<160, 256>>>(Wih0f, Whh0f, bih0f, Wih0b, Whh0b, bih0b,
                               Wih1f, Whh1f, bih1f, Wih1b, Whh1b, bih1b, fc1_W);
    sort_kernel<<<1, BB>>>(text_len);
    embw_kernel<<<(VV + 31) / 32, 128>>>(emb);
    gru_layer0<<<148, 128>>>(text, text_len, bhh0f, bhh0b);
    gx1_kernel<<<dim3(BB, TT / 32), 128>>>(text_len);
    gru_layer1<<<148, 128>>>(text_len, bhh1f, bhh1b);
    fc_kernel<<<BB, 128>>>(fc1_b, fc2_W, fc2_b, out);
}